// round 1
// baseline (speedup 1.0000x reference)
#include <cuda_runtime.h>
#include <math.h>

#define BB 8
#define NN 512
#define KK 32
#define DD 128
#define HH 128
#define PP 8
#define NODES (BB*NN)

// Scratch (allocation-free rule: __device__ globals)
__device__ float g_pg[NODES*PP*3];   // global points per node
__device__ float g_R[NODES*9];       // frames
__device__ float g_t[NODES*3];       // translations
__device__ float g_s1[NODES*HH];     // static part of layer-1 pre-activation (incl bias)

// ---------------------------------------------------------------------------
// Kernel 1: per-node frame, local/global points, static layer-1 contribution
// ---------------------------------------------------------------------------
__global__ void node_prep_kernel(const float* __restrict__ hV_g,
                                 const float* __restrict__ X,
                                 const float* __restrict__ Wp,
                                 const float* __restrict__ bp,
                                 const float* __restrict__ Wm1,
                                 const float* __restrict__ bm1)
{
    int node = blockIdx.x;
    int t = threadIdx.x;
    __shared__ float hv[DD];
    __shared__ float pl[24];
    __shared__ float plnorm[8];
    __shared__ float Rn[9];
    __shared__ float tn[3];

    hv[t] = hV_g[(size_t)node*DD + t];
    __syncthreads();

    if (t == 0) {
        const float* x = X + (size_t)node*9;
        float Xn0=x[0],Xn1=x[1],Xn2=x[2];
        float Xa0=x[3],Xa1=x[4],Xa2=x[5];
        float Xc0=x[6],Xc1=x[7],Xc2=x[8];
        float v10=Xc0-Xa0, v11=Xc1-Xa1, v12=Xc2-Xa2;
        float v20=Xn0-Xa0, v21=Xn1-Xa1, v22=Xn2-Xa2;
        float inv1 = rsqrtf(v10*v10+v11*v11+v12*v12+1e-8f);
        float e10=v10*inv1, e11=v11*inv1, e12=v12*inv1;
        float dp = e10*v20+e11*v21+e12*v22;
        float u20=v20-e10*dp, u21=v21-e11*dp, u22=v22-e12*dp;
        float inv2 = rsqrtf(u20*u20+u21*u21+u22*u22+1e-8f);
        float e20=u20*inv2, e21=u21*inv2, e22=u22*inv2;
        float e30=e11*e22-e12*e21;
        float e31=e12*e20-e10*e22;
        float e32=e10*e21-e11*e20;
        // R columns are e1,e2,e3  -> R[i][j], Rn[i*3+j]
        Rn[0]=e10; Rn[1]=e20; Rn[2]=e30;
        Rn[3]=e11; Rn[4]=e21; Rn[5]=e31;
        Rn[6]=e12; Rn[7]=e22; Rn[8]=e32;
        tn[0]=Xa0*0.1f; tn[1]=Xa1*0.1f; tn[2]=Xa2*0.1f;
    }
    if (t < 24) {
        float acc = bp[t];
        #pragma unroll 8
        for (int d = 0; d < DD; ++d) acc += hv[d] * Wp[d*24 + t];
        pl[t] = acc;
    }
    __syncthreads();

    if (t < 8) {
        float a=pl[t*3+0], b=pl[t*3+1], c=pl[t*3+2];
        plnorm[t] = sqrtf(a*a+b*b+c*c + 1e-8f);
    }
    if (t < 24) {
        int p = t/3, i = t%3;
        float pg = tn[i] + Rn[i*3+0]*pl[p*3+0] + Rn[i*3+1]*pl[p*3+1] + Rn[i*3+2]*pl[p*3+2];
        g_pg[(size_t)node*24 + t] = pg;
    }
    if (t < 9) g_R[(size_t)node*9 + t] = Rn[t];
    if (t < 3) g_t[(size_t)node*3 + t] = tn[t];
    __syncthreads();

    // static layer-1 contribution: rows 0..127 (node h_V), 384..407 (pl), 408..415 (plnorm)
    float s = bm1[t];
    #pragma unroll 4
    for (int d = 0; d < DD; ++d) s += hv[d] * Wm1[d*HH + t];
    #pragma unroll
    for (int j = 0; j < 24; ++j) s += pl[j] * Wm1[(384+j)*HH + t];
    #pragma unroll
    for (int p = 0; p < 8; ++p) s += plnorm[p] * Wm1[(408+p)*HH + t];
    g_s1[(size_t)node*HH + t] = s;
}

// ---------------------------------------------------------------------------
// Register-tiled smem-broadcast GEMM chunk: acc[e] += msg[e][r] * W[r][t]
// W is row-major [ROWS x HH]; m rows have STRIDE floats. Double-buffered
// weight loads to hide L1/L2 latency.
// ---------------------------------------------------------------------------
template<int ROWS, int STRIDE>
__device__ __forceinline__ void gemm_part(float acc[KK], const float* __restrict__ W,
                                          const float* m, int t)
{
    float w0 = W[t], w1 = W[HH+t], w2 = W[2*HH+t], w3 = W[3*HH+t];
    #pragma unroll 1
    for (int r = 0; r < ROWS; r += 4) {
        float n0=0.f, n1=0.f, n2=0.f, n3=0.f;
        if (r + 4 < ROWS) {
            const float* Wn = W + (r+4)*HH;
            n0 = Wn[t]; n1 = Wn[HH+t]; n2 = Wn[2*HH+t]; n3 = Wn[3*HH+t];
        }
        #pragma unroll
        for (int e = 0; e < KK; ++e) {
            float4 v = *(const float4*)(m + e*STRIDE + r);
            acc[e] = fmaf(v.x, w0, acc[e]);
            acc[e] = fmaf(v.y, w1, acc[e]);
            acc[e] = fmaf(v.z, w2, acc[e]);
            acc[e] = fmaf(v.w, w3, acc[e]);
        }
        w0=n0; w1=n1; w2=n2; w3=n3;
    }
}

__device__ __forceinline__ float warp_sum(float v) {
    #pragma unroll
    for (int o = 16; o; o >>= 1) v += __shfl_xor_sync(0xffffffffu, v, o);
    return v;
}

// smem layout (floats)
#define SM_MSG   0         // 32*296 = 9472
#define SM_M1    9472      // 4096
#define SM_M2    13568     // 4096
#define SM_HV    17664     // 128
#define SM_S1    17792     // 128
#define SM_HS    17920     // 128
#define SM_D1    18048     // 512
#define SM_RN    18560     // 12
#define SM_TN    18572     // 4
#define SM_PGN   18576     // 24
#define SM_MA    18600     // 32
#define SM_RED   18632     // 8
#define SM_FLOATS 18640
#define SMEM_BYTES (SM_FLOATS*4)

// ---------------------------------------------------------------------------
// Kernel 2: per-node edge messages + MLP + reduce + LN + dense + LN
// ---------------------------------------------------------------------------
__global__ void __launch_bounds__(128)
msg_kernel(const float* __restrict__ hV_g, const float* __restrict__ hE_g,
           const float* __restrict__ maskV_g, const float* __restrict__ maskA_g,
           const float* __restrict__ Wm1,
           const float* __restrict__ Wm2, const float* __restrict__ bm2,
           const float* __restrict__ Wm3, const float* __restrict__ bm3,
           const float* __restrict__ g1, const float* __restrict__ be1,
           const float* __restrict__ Wd1, const float* __restrict__ bd1,
           const float* __restrict__ Wd2, const float* __restrict__ bd2,
           const float* __restrict__ g2, const float* __restrict__ be2,
           const int* __restrict__ Eidx, float* __restrict__ out)
{
    extern __shared__ float sm[];
    float* msg = sm + SM_MSG;
    float* m1  = sm + SM_M1;
    float* m2  = sm + SM_M2;
    float* hv  = sm + SM_HV;
    float* s1  = sm + SM_S1;
    float* hs  = sm + SM_HS;
    float* d1s = sm + SM_D1;
    float* Rn  = sm + SM_RN;
    float* tn  = sm + SM_TN;
    float* pgn = sm + SM_PGN;
    float* mA  = sm + SM_MA;
    float* red = sm + SM_RED;

    int node = blockIdx.x;
    int batch = node / NN;
    int t = threadIdx.x;
    int w = t >> 5, lane = t & 31;

    hv[t] = hV_g[(size_t)node*DD + t];
    s1[t] = g_s1[(size_t)node*HH + t];
    if (t < 24) pgn[t] = g_pg[(size_t)node*24 + t];
    if (t < 9)  Rn[t] = g_R[(size_t)node*9 + t];
    if (t >= 12 && t < 15) tn[t-12] = g_t[(size_t)node*3 + (t-12)];
    if (t >= 32 && t < 64) mA[t-32] = maskA_g[(size_t)node*KK + (t-32)];
    __syncthreads();

    // ------- fill edge features: msg[e][0..295] -------
    // rows: 0..127 h_E | 128..255 nbr_hV | 256..279 nbr_pl | 280..287 npl_norm | 288..295 npg_norm
    const int* eidx = Eidx + (size_t)node*KK;
    for (int e = w; e < KK; e += 4) {
        int j = eidx[e];
        const float4* hE4  = (const float4*)(hE_g + ((size_t)node*KK + e)*DD);
        const float4* hVj4 = (const float4*)(hV_g + (size_t)(batch*NN + j)*DD);
        float* row = msg + e*296;
        ((float4*)row)[lane]       = hE4[lane];
        ((float4*)(row+128))[lane] = hVj4[lane];
        if (lane < 8) {
            int p = lane;
            const float* qg = g_pg + (size_t)(batch*NN + j)*24 + p*3;
            float q0 = qg[0], q1 = qg[1], q2 = qg[2];
            float d0 = pgn[p*3+0]-q0, d1 = pgn[p*3+1]-q1, d2 = pgn[p*3+2]-q2;
            float c0 = q0 - tn[0], c1 = q1 - tn[1], c2 = q2 - tn[2];
            float l0 = Rn[0]*c0 + Rn[3]*c1 + Rn[6]*c2;
            float l1 = Rn[1]*c0 + Rn[4]*c1 + Rn[7]*c2;
            float l2 = Rn[2]*c0 + Rn[5]*c1 + Rn[8]*c2;
            row[256+p*3+0] = l0; row[256+p*3+1] = l1; row[256+p*3+2] = l2;
            row[280+p] = sqrtf(l0*l0+l1*l1+l2*l2 + 1e-8f);
            row[288+p] = sqrtf(d0*d0+d1*d1+d2*d2 + 1e-8f);
        }
    }
    __syncthreads();

    // ------- layer 1 (edge part; static part & bias preloaded) -------
    float acc[KK];
    {
        float s = s1[t];
        #pragma unroll
        for (int e = 0; e < KK; ++e) acc[e] = s;
    }
    gemm_part<256,296>(acc, Wm1 + 128*HH, msg, t);        // h_E + nbr_hV rows
    gemm_part<40,296>(acc, Wm1 + 416*HH, msg + 256, t);   // geometry rows
    #pragma unroll
    for (int e = 0; e < KK; ++e) m1[e*HH + t] = fmaxf(acc[e], 0.f);
    __syncthreads();

    // ------- layer 2 -------
    {
        float b = bm2[t];
        #pragma unroll
        for (int e = 0; e < KK; ++e) acc[e] = b;
    }
    gemm_part<128,128>(acc, Wm2, m1, t);
    #pragma unroll
    for (int e = 0; e < KK; ++e) m2[e*HH + t] = fmaxf(acc[e], 0.f);
    __syncthreads();

    // ------- layer 3 (no relu) -------
    {
        float b = bm3[t];
        #pragma unroll
        for (int e = 0; e < KK; ++e) acc[e] = b;
    }
    gemm_part<128,128>(acc, Wm3, m2, t);

    // mask + mean over K
    float nm = 0.f;
    #pragma unroll
    for (int e = 0; e < KK; ++e) nm += acc[e] * mA[e];
    nm *= (1.0f / KK);

    // ------- LN1(h_V + node_m) -------
    float x = hv[t] + nm;
    float sA = warp_sum(x);
    if (!lane) red[w] = sA;
    __syncthreads();
    float mu = (red[0]+red[1]+red[2]+red[3]) * (1.0f/HH);
    float dx = x - mu;
    float sB = warp_sum(dx*dx);
    __syncthreads();
    if (!lane) red[w] = sB;
    __syncthreads();
    float var = (red[0]+red[1]+red[2]+red[3]) * (1.0f/HH);
    float xn = dx * rsqrtf(var + 1e-5f) * g1[t] + be1[t];
    hs[t] = xn;
    __syncthreads();

    // ------- dense: 128 -> 512 relu -> 128 -------
    float a0 = bd1[t], a1 = bd1[t+128], a2 = bd1[t+256], a3 = bd1[t+384];
    #pragma unroll 4
    for (int r = 0; r < HH; ++r) {
        float hr = hs[r];
        const float* wr = Wd1 + r*512 + t;
        a0 = fmaf(hr, wr[0],   a0);
        a1 = fmaf(hr, wr[128], a1);
        a2 = fmaf(hr, wr[256], a2);
        a3 = fmaf(hr, wr[384], a3);
    }
    d1s[t]     = fmaxf(a0, 0.f);
    d1s[t+128] = fmaxf(a1, 0.f);
    d1s[t+256] = fmaxf(a2, 0.f);
    d1s[t+384] = fmaxf(a3, 0.f);
    __syncthreads();

    float o = bd2[t];
    #pragma unroll 2
    for (int r = 0; r < 512; r += 4) {
        float4 dv = *(const float4*)(d1s + r);
        o = fmaf(dv.x, Wd2[(r+0)*HH + t], o);
        o = fmaf(dv.y, Wd2[(r+1)*HH + t], o);
        o = fmaf(dv.z, Wd2[(r+2)*HH + t], o);
        o = fmaf(dv.w, Wd2[(r+3)*HH + t], o);
    }

    // ------- LN2(h + dense), mask_V -------
    float x2 = hs[t] + o;
    __syncthreads();  // red reuse safety
    float s2A = warp_sum(x2);
    if (!lane) red[w] = s2A;
    __syncthreads();
    float mu2 = (red[0]+red[1]+red[2]+red[3]) * (1.0f/HH);
    float dx2 = x2 - mu2;
    float s2B = warp_sum(dx2*dx2);
    __syncthreads();
    if (!lane) red[w] = s2B;
    __syncthreads();
    float var2 = (red[0]+red[1]+red[2]+red[3]) * (1.0f/HH);
    float y = (dx2 * rsqrtf(var2 + 1e-5f) * g2[t] + be2[t]) * maskV_g[node];
    out[(size_t)node*HH + t] = y;
}

// ---------------------------------------------------------------------------
extern "C" void kernel_launch(void* const* d_in, const int* in_sizes, int n_in,
                              void* d_out, int out_size)
{
    const float* hV    = (const float*)d_in[0];
    const float* hE    = (const float*)d_in[1];
    const float* X     = (const float*)d_in[2];
    const float* maskV = (const float*)d_in[3];
    const float* maskA = (const float*)d_in[4];
    const float* Wp    = (const float*)d_in[5];
    const float* bp    = (const float*)d_in[6];
    const float* Wm1   = (const float*)d_in[7];
    const float* bm1   = (const float*)d_in[8];
    const float* Wm2   = (const float*)d_in[9];
    const float* bm2   = (const float*)d_in[10];
    const float* Wm3   = (const float*)d_in[11];
    const float* bm3   = (const float*)d_in[12];
    const float* g1    = (const float*)d_in[13];
    const float* be1   = (const float*)d_in[14];
    const float* Wd1   = (const float*)d_in[15];
    const float* bd1   = (const float*)d_in[16];
    const float* Wd2   = (const float*)d_in[17];
    const float* bd2   = (const float*)d_in[18];
    const float* g2    = (const float*)d_in[19];
    const float* be2   = (const float*)d_in[20];
    const int*   Eidx  = (const int*)d_in[21];
    float* out = (float*)d_out;

    cudaFuncSetAttribute(msg_kernel, cudaFuncAttributeMaxDynamicSharedMemorySize, SMEM_BYTES);

    node_prep_kernel<<<NODES, 128>>>(hV, X, Wp, bp, Wm1, bm1);
    msg_kernel<<<NODES, 128, SMEM_BYTES>>>(hV, hE, maskV, maskA, Wm1,
                                           Wm2, bm2, Wm3, bm3, g1, be1,
                                           Wd1, bd1, Wd2, bd2, g2, be2,
                                           Eidx, out);

    // second output: h_E passthrough
    long long hcount = (long long)NODES * HH;
    if ((long long)out_size > hcount) {
        long long n = (long long)out_size - hcount;
        long long emax = (long long)BB*NN*KK*DD;
        if (n > emax) n = emax;
        cudaMemcpyAsync(out + hcount, hE, (size_t)n * sizeof(float),
                        cudaMemcpyDeviceToDevice);
    }
}

// round 2
// speedup vs baseline: 1.2088x; 1.2088x over previous
#include <cuda_runtime.h>
#include <math.h>

#define BB 8
#define NN 512
#define KK 32
#define DD 128
#define HH 128
#define PP 8
#define NODES (BB*NN)

// Scratch (allocation-free rule: __device__ globals)
__device__ float g_pg[NODES*PP*3];   // global points per node
__device__ float g_R[NODES*9];       // frames
__device__ float g_t[NODES*3];       // translations
__device__ float g_s1[NODES*HH];     // static part of layer-1 pre-activation (incl bias)

// ---------------------------------------------------------------------------
// Kernel 1: per-node frame, local/global points, static layer-1 contribution
// ---------------------------------------------------------------------------
__global__ void node_prep_kernel(const float* __restrict__ hV_g,
                                 const float* __restrict__ X,
                                 const float* __restrict__ Wp,
                                 const float* __restrict__ bp,
                                 const float* __restrict__ Wm1,
                                 const float* __restrict__ bm1)
{
    int node = blockIdx.x;
    int t = threadIdx.x;
    __shared__ float hv[DD];
    __shared__ float pl[24];
    __shared__ float plnorm[8];
    __shared__ float Rn[9];
    __shared__ float tn[3];

    hv[t] = hV_g[(size_t)node*DD + t];
    __syncthreads();

    if (t == 0) {
        const float* x = X + (size_t)node*9;
        float Xn0=x[0],Xn1=x[1],Xn2=x[2];
        float Xa0=x[3],Xa1=x[4],Xa2=x[5];
        float Xc0=x[6],Xc1=x[7],Xc2=x[8];
        float v10=Xc0-Xa0, v11=Xc1-Xa1, v12=Xc2-Xa2;
        float v20=Xn0-Xa0, v21=Xn1-Xa1, v22=Xn2-Xa2;
        float inv1 = rsqrtf(v10*v10+v11*v11+v12*v12+1e-8f);
        float e10=v10*inv1, e11=v11*inv1, e12=v12*inv1;
        float dp = e10*v20+e11*v21+e12*v22;
        float u20=v20-e10*dp, u21=v21-e11*dp, u22=v22-e12*dp;
        float inv2 = rsqrtf(u20*u20+u21*u21+u22*u22+1e-8f);
        float e20=u20*inv2, e21=u21*inv2, e22=u22*inv2;
        float e30=e11*e22-e12*e21;
        float e31=e12*e20-e10*e22;
        float e32=e10*e21-e11*e20;
        Rn[0]=e10; Rn[1]=e20; Rn[2]=e30;
        Rn[3]=e11; Rn[4]=e21; Rn[5]=e31;
        Rn[6]=e12; Rn[7]=e22; Rn[8]=e32;
        tn[0]=Xa0*0.1f; tn[1]=Xa1*0.1f; tn[2]=Xa2*0.1f;
    }
    if (t < 24) {
        float acc = bp[t];
        #pragma unroll 8
        for (int d = 0; d < DD; ++d) acc += hv[d] * Wp[d*24 + t];
        pl[t] = acc;
    }
    __syncthreads();

    if (t < 8) {
        float a=pl[t*3+0], b=pl[t*3+1], c=pl[t*3+2];
        plnorm[t] = sqrtf(a*a+b*b+c*c + 1e-8f);
    }
    if (t < 24) {
        int p = t/3, i = t%3;
        float pg = tn[i] + Rn[i*3+0]*pl[p*3+0] + Rn[i*3+1]*pl[p*3+1] + Rn[i*3+2]*pl[p*3+2];
        g_pg[(size_t)node*24 + t] = pg;
    }
    if (t < 9) g_R[(size_t)node*9 + t] = Rn[t];
    if (t < 3) g_t[(size_t)node*3 + t] = tn[t];
    __syncthreads();

    // static layer-1 contribution: rows 0..127 (node h_V), 384..407 (pl), 408..415 (plnorm)
    float s = bm1[t];
    #pragma unroll 4
    for (int d = 0; d < DD; ++d) s += hv[d] * Wm1[d*HH + t];
    #pragma unroll
    for (int j = 0; j < 24; ++j) s += pl[j] * Wm1[(384+j)*HH + t];
    #pragma unroll
    for (int p = 0; p < 8; ++p) s += plnorm[p] * Wm1[(408+p)*HH + t];
    g_s1[(size_t)node*HH + t] = s;
}

// ---------------------------------------------------------------------------
// 16-acc smem-broadcast GEMM chunk: acc[e] += m[e][r] * W[r][c]
// ---------------------------------------------------------------------------
template<int ROWS, int STRIDE>
__device__ __forceinline__ void gemm16(float acc[16], const float* __restrict__ W,
                                       const float* m, int c)
{
    float w0 = W[c], w1 = W[HH+c], w2 = W[2*HH+c], w3 = W[3*HH+c];
    #pragma unroll 1
    for (int r = 0; r < ROWS; r += 4) {
        float n0=0.f, n1=0.f, n2=0.f, n3=0.f;
        if (r + 4 < ROWS) {
            const float* Wn = W + (r+4)*HH;
            n0 = Wn[c]; n1 = Wn[HH+c]; n2 = Wn[2*HH+c]; n3 = Wn[3*HH+c];
        }
        #pragma unroll
        for (int e = 0; e < 16; ++e) {
            float4 v = *(const float4*)(m + e*STRIDE + r);
            acc[e] = fmaf(v.x, w0, acc[e]);
            acc[e] = fmaf(v.y, w1, acc[e]);
            acc[e] = fmaf(v.z, w2, acc[e]);
            acc[e] = fmaf(v.w, w3, acc[e]);
        }
        w0=n0; w1=n1; w2=n2; w3=n3;
    }
}

__device__ __forceinline__ float warp_sum(float v) {
    #pragma unroll
    for (int o = 16; o; o >>= 1) v += __shfl_xor_sync(0xffffffffu, v, o);
    return v;
}

// smem layout (floats)
#define SM_BUF   0         // 32*128 = 4096 : h_E stage -> nbr_hV stage -> m2
#define SM_M1    4096      // 4096
#define SM_GEO   8192      // 32*40 = 1280
#define SM_HV    9472      // 128
#define SM_S1    9600      // 128
#define SM_HS    9728      // 128
#define SM_D1    9856      // 512
#define SM_RN    10368     // 12
#define SM_TN    10380     // 4
#define SM_PGN   10384     // 24
#define SM_MA    10408     // 32
#define SM_RED   10440     // 8
#define SM_PD    10448     // 256
#define SM_EIX   10704     // 32 (ints)
#define SM_FLOATS 10736
#define SMEM_BYTES (SM_FLOATS*4)

// ---------------------------------------------------------------------------
// Kernel 2: per-node edge messages + MLP + reduce + LN + dense + LN
// 256 threads: group g = t>>7 owns edges [g*16, g*16+16); col c = t&127.
// ---------------------------------------------------------------------------
__global__ void __launch_bounds__(256, 4)
msg_kernel(const float* __restrict__ hV_g, const float* __restrict__ hE_g,
           const float* __restrict__ maskV_g, const float* __restrict__ maskA_g,
           const float* __restrict__ Wm1,
           const float* __restrict__ Wm2, const float* __restrict__ bm2,
           const float* __restrict__ Wm3, const float* __restrict__ bm3,
           const float* __restrict__ g1, const float* __restrict__ be1,
           const float* __restrict__ Wd1, const float* __restrict__ bd1,
           const float* __restrict__ Wd2, const float* __restrict__ bd2,
           const float* __restrict__ g2, const float* __restrict__ be2,
           const int* __restrict__ Eidx, float* __restrict__ out)
{
    extern __shared__ float sm[];
    float* buf = sm + SM_BUF;
    float* m1  = sm + SM_M1;
    float* geo = sm + SM_GEO;
    float* hv  = sm + SM_HV;
    float* s1  = sm + SM_S1;
    float* hs  = sm + SM_HS;
    float* d1s = sm + SM_D1;
    float* Rn  = sm + SM_RN;
    float* tn  = sm + SM_TN;
    float* pgn = sm + SM_PGN;
    float* mA  = sm + SM_MA;
    float* red = sm + SM_RED;
    float* pd  = sm + SM_PD;
    int*   eix = (int*)(sm + SM_EIX);

    int node = blockIdx.x;
    int batch = node / NN;
    int t = threadIdx.x;
    int w = t >> 5, lane = t & 31;
    int g = t >> 7, c = t & 127;
    int e0 = g * 16;

    if (t < 128) {
        hv[t] = hV_g[(size_t)node*DD + t];
        s1[t] = g_s1[(size_t)node*HH + t];
    } else {
        int u = t - 128;
        if (u < 24) pgn[u] = g_pg[(size_t)node*24 + u];
        else if (u < 33) Rn[u-24] = g_R[(size_t)node*9 + (u-24)];
        else if (u < 36) tn[u-33] = g_t[(size_t)node*3 + (u-33)];
        else if (u >= 64 && u < 96) mA[u-64] = maskA_g[(size_t)node*KK + (u-64)];
        else if (u >= 96 && u < 128) eix[u-96] = Eidx[(size_t)node*KK + (u-96)];
    }
    __syncthreads();

    // ---------------- phase 1: stage h_E (coalesced copy) ----------------
    {
        const float4* src = (const float4*)(hE_g + (size_t)node*KK*DD);
        float4* dst = (float4*)buf;
        #pragma unroll
        for (int i = 0; i < 4; ++i) dst[t + i*256] = src[t + i*256];
    }
    // geometry rows while staging: warp w handles edges w, w+8, w+16, w+24
    #pragma unroll
    for (int ii = 0; ii < 4; ++ii) {
        int e = w + ii*8;
        if (lane < 8) {
            int p = lane;
            int j = eix[e];
            const float* qg = g_pg + (size_t)(batch*NN + j)*24 + p*3;
            float q0 = qg[0], q1 = qg[1], q2 = qg[2];
            float d0 = pgn[p*3+0]-q0, d1 = pgn[p*3+1]-q1, d2 = pgn[p*3+2]-q2;
            float c0 = q0 - tn[0], c1 = q1 - tn[1], c2 = q2 - tn[2];
            float l0 = Rn[0]*c0 + Rn[3]*c1 + Rn[6]*c2;
            float l1 = Rn[1]*c0 + Rn[4]*c1 + Rn[7]*c2;
            float l2 = Rn[2]*c0 + Rn[5]*c1 + Rn[8]*c2;
            float* row = geo + e*40;
            row[p*3+0] = l0; row[p*3+1] = l1; row[p*3+2] = l2;
            row[24+p] = sqrtf(l0*l0+l1*l1+l2*l2 + 1e-8f);
            row[32+p] = sqrtf(d0*d0+d1*d1+d2*d2 + 1e-8f);
        }
    }
    __syncthreads();

    // ---------------- layer 1 ----------------
    float acc[16];
    {
        float s = s1[c];
        #pragma unroll
        for (int e = 0; e < 16; ++e) acc[e] = s;
    }
    gemm16<128,128>(acc, Wm1 + 128*HH, buf + e0*128, c);   // h_E rows 128..255
    __syncthreads();

    // ---------------- phase 2: stage nbr_hV (gather) ----------------
    #pragma unroll
    for (int ii = 0; ii < 4; ++ii) {
        int e = w + ii*8;
        int j = eix[e];
        const float4* src = (const float4*)(hV_g + (size_t)(batch*NN + j)*DD);
        ((float4*)(buf + e*128))[lane] = src[lane];
    }
    __syncthreads();

    gemm16<128,128>(acc, Wm1 + 256*HH, buf + e0*128, c);   // nbr_hV rows 256..383
    gemm16<40,40>  (acc, Wm1 + 416*HH, geo + e0*40,  c);   // geometry rows 416..455
    #pragma unroll
    for (int e = 0; e < 16; ++e) m1[(e0+e)*128 + c] = fmaxf(acc[e], 0.f);
    __syncthreads();

    // ---------------- layer 2 (writes m2 = buf) ----------------
    {
        float b = bm2[c];
        #pragma unroll
        for (int e = 0; e < 16; ++e) acc[e] = b;
    }
    gemm16<128,128>(acc, Wm2, m1 + e0*128, c);
    __syncthreads();   // all reads of buf (stage-2) done before overwrite
    #pragma unroll
    for (int e = 0; e < 16; ++e) buf[(e0+e)*128 + c] = fmaxf(acc[e], 0.f);
    __syncthreads();

    // ---------------- layer 3 (no relu) ----------------
    {
        float b = bm3[c];
        #pragma unroll
        for (int e = 0; e < 16; ++e) acc[e] = b;
    }
    gemm16<128,128>(acc, Wm3, buf + e0*128, c);

    // mask + partial mean over this group's edges
    {
        float nmp = 0.f;
        #pragma unroll
        for (int e = 0; e < 16; ++e) nmp += acc[e] * mA[e0+e];
        pd[g*128 + c] = nmp;
    }
    __syncthreads();

    // ---------------- LN1(h_V + node_m)  (threads 0..127) ----------------
    float x = 0.f, dx = 0.f;
    if (t < 128) {
        float nm = (pd[c] + pd[128+c]) * (1.0f/KK);
        x = hv[c] + nm;
        float sA = warp_sum(x);
        if (!lane) red[w] = sA;
    }
    __syncthreads();
    if (t < 128) {
        float mu = (red[0]+red[1]+red[2]+red[3]) * (1.0f/HH);
        dx = x - mu;
        float sB = warp_sum(dx*dx);
        __syncwarp();
        if (!lane) red[w+4] = sB;
    }
    __syncthreads();
    if (t < 128) {
        float var = (red[4]+red[5]+red[6]+red[7]) * (1.0f/HH);
        hs[c] = dx * rsqrtf(var + 1e-5f) * g1[c] + be1[c];
    }
    __syncthreads();

    // ---------------- dense1: 128 -> 512 relu (each thread 2 cols) ----------------
    {
        int c0 = t, c1 = t + 256;
        float a0 = bd1[c0], a1 = bd1[c1];
        #pragma unroll 4
        for (int r = 0; r < HH; ++r) {
            float hr = hs[r];
            a0 = fmaf(hr, Wd1[r*512 + c0], a0);
            a1 = fmaf(hr, Wd1[r*512 + c1], a1);
        }
        d1s[c0] = fmaxf(a0, 0.f);
        d1s[c1] = fmaxf(a1, 0.f);
    }
    __syncthreads();

    // ---------------- dense2: 512 -> 128, row-split across groups ----------------
    {
        float o = 0.f;
        const float* dbase = d1s + g*256;
        const float* Wbase = Wd2 + (size_t)g*256*128;
        #pragma unroll 2
        for (int r = 0; r < 256; r += 4) {
            float4 dv = *(const float4*)(dbase + r);
            o = fmaf(dv.x, Wbase[(r+0)*128 + c], o);
            o = fmaf(dv.y, Wbase[(r+1)*128 + c], o);
            o = fmaf(dv.z, Wbase[(r+2)*128 + c], o);
            o = fmaf(dv.w, Wbase[(r+3)*128 + c], o);
        }
        pd[g*128 + c] = o;
    }
    __syncthreads();

    // ---------------- LN2(h + dense), mask_V  (threads 0..127) ----------------
    float x2 = 0.f, dx2 = 0.f;
    if (t < 128) {
        x2 = hs[c] + bd2[c] + pd[c] + pd[128+c];
        float sA = warp_sum(x2);
        if (!lane) red[w] = sA;
    }
    __syncthreads();
    if (t < 128) {
        float mu2 = (red[0]+red[1]+red[2]+red[3]) * (1.0f/HH);
        dx2 = x2 - mu2;
        float sB = warp_sum(dx2*dx2);
        __syncwarp();
        if (!lane) red[w+4] = sB;
    }
    __syncthreads();
    if (t < 128) {
        float var2 = (red[4]+red[5]+red[6]+red[7]) * (1.0f/HH);
        float y = (dx2 * rsqrtf(var2 + 1e-5f) * g2[c] + be2[c]) * maskV_g[node];
        out[(size_t)node*HH + c] = y;
    }
}

// ---------------------------------------------------------------------------
extern "C" void kernel_launch(void* const* d_in, const int* in_sizes, int n_in,
                              void* d_out, int out_size)
{
    const float* hV    = (const float*)d_in[0];
    const float* hE    = (const float*)d_in[1];
    const float* X     = (const float*)d_in[2];
    const float* maskV = (const float*)d_in[3];
    const float* maskA = (const float*)d_in[4];
    const float* Wp    = (const float*)d_in[5];
    const float* bp    = (const float*)d_in[6];
    const float* Wm1   = (const float*)d_in[7];
    const float* bm1   = (const float*)d_in[8];
    const float* Wm2   = (const float*)d_in[9];
    const float* bm2   = (const float*)d_in[10];
    const float* Wm3   = (const float*)d_in[11];
    const float* bm3   = (const float*)d_in[12];
    const float* g1    = (const float*)d_in[13];
    const float* be1   = (const float*)d_in[14];
    const float* Wd1   = (const float*)d_in[15];
    const float* bd1   = (const float*)d_in[16];
    const float* Wd2   = (const float*)d_in[17];
    const float* bd2   = (const float*)d_in[18];
    const float* g2    = (const float*)d_in[19];
    const float* be2   = (const float*)d_in[20];
    const int*   Eidx  = (const int*)d_in[21];
    float* out = (float*)d_out;

    node_prep_kernel<<<NODES, 128>>>(hV, X, Wp, bp, Wm1, bm1);
    msg_kernel<<<NODES, 256, SMEM_BYTES>>>(hV, hE, maskV, maskA, Wm1,
                                           Wm2, bm2, Wm3, bm3, g1, be1,
                                           Wd1, bd1, Wd2, bd2, g2, be2,
                                           Eidx, out);

    // second output: h_E passthrough
    long long hcount = (long long)NODES * HH;
    if ((long long)out_size > hcount) {
        long long n = (long long)out_size - hcount;
        long long emax = (long long)BB*NN*KK*DD;
        if (n > emax) n = emax;
        cudaMemcpyAsync(out + hcount, hE, (size_t)n * sizeof(float),
                        cudaMemcpyDeviceToDevice);
    }
}

// round 3
// speedup vs baseline: 1.4165x; 1.1719x over previous
#include <cuda_runtime.h>
#include <math.h>

#define BB 8
#define NN 512
#define KK 32
#define DD 128
#define HH 128
#define PP 8
#define NODES (BB*NN)

// Scratch (allocation-free rule: __device__ globals)
__device__ float g_pg[NODES*PP*3];   // global points per node
__device__ float g_R[NODES*9];       // frames
__device__ float g_t[NODES*3];       // translations
__device__ float g_s1[NODES*HH];     // static part of layer-1 pre-activation (incl bias)

// ---------------------------------------------------------------------------
// Kernel 1: per-node frame, local/global points, static layer-1 contribution
// ---------------------------------------------------------------------------
__global__ void node_prep_kernel(const float* __restrict__ hV_g,
                                 const float* __restrict__ X,
                                 const float* __restrict__ Wp,
                                 const float* __restrict__ bp,
                                 const float* __restrict__ Wm1,
                                 const float* __restrict__ bm1)
{
    int node = blockIdx.x;
    int t = threadIdx.x;
    __shared__ float hv[DD];
    __shared__ float pl[24];
    __shared__ float plnorm[8];
    __shared__ float Rn[9];
    __shared__ float tn[3];

    hv[t] = hV_g[(size_t)node*DD + t];
    __syncthreads();

    if (t == 0) {
        const float* x = X + (size_t)node*9;
        float Xn0=x[0],Xn1=x[1],Xn2=x[2];
        float Xa0=x[3],Xa1=x[4],Xa2=x[5];
        float Xc0=x[6],Xc1=x[7],Xc2=x[8];
        float v10=Xc0-Xa0, v11=Xc1-Xa1, v12=Xc2-Xa2;
        float v20=Xn0-Xa0, v21=Xn1-Xa1, v22=Xn2-Xa2;
        float inv1 = rsqrtf(v10*v10+v11*v11+v12*v12+1e-8f);
        float e10=v10*inv1, e11=v11*inv1, e12=v12*inv1;
        float dp = e10*v20+e11*v21+e12*v22;
        float u20=v20-e10*dp, u21=v21-e11*dp, u22=v22-e12*dp;
        float inv2 = rsqrtf(u20*u20+u21*u21+u22*u22+1e-8f);
        float e20=u20*inv2, e21=u21*inv2, e22=u22*inv2;
        float e30=e11*e22-e12*e21;
        float e31=e12*e20-e10*e22;
        float e32=e10*e21-e11*e20;
        Rn[0]=e10; Rn[1]=e20; Rn[2]=e30;
        Rn[3]=e11; Rn[4]=e21; Rn[5]=e31;
        Rn[6]=e12; Rn[7]=e22; Rn[8]=e32;
        tn[0]=Xa0*0.1f; tn[1]=Xa1*0.1f; tn[2]=Xa2*0.1f;
    }
    if (t < 24) {
        float acc = bp[t];
        #pragma unroll 8
        for (int d = 0; d < DD; ++d) acc += hv[d] * Wp[d*24 + t];
        pl[t] = acc;
    }
    __syncthreads();

    if (t < 8) {
        float a=pl[t*3+0], b=pl[t*3+1], c=pl[t*3+2];
        plnorm[t] = sqrtf(a*a+b*b+c*c + 1e-8f);
    }
    if (t < 24) {
        int p = t/3, i = t%3;
        float pg = tn[i] + Rn[i*3+0]*pl[p*3+0] + Rn[i*3+1]*pl[p*3+1] + Rn[i*3+2]*pl[p*3+2];
        g_pg[(size_t)node*24 + t] = pg;
    }
    if (t < 9) g_R[(size_t)node*9 + t] = Rn[t];
    if (t < 3) g_t[(size_t)node*3 + t] = tn[t];
    __syncthreads();

    // static layer-1 contribution: rows 0..127 (node h_V), 384..407 (pl), 408..415 (plnorm)
    float s = bm1[t];
    #pragma unroll 4
    for (int d = 0; d < DD; ++d) s += hv[d] * Wm1[d*HH + t];
    #pragma unroll
    for (int j = 0; j < 24; ++j) s += pl[j] * Wm1[(384+j)*HH + t];
    #pragma unroll
    for (int p = 0; p < 8; ++p) s += plnorm[p] * Wm1[(408+p)*HH + t];
    g_s1[(size_t)node*HH + t] = s;
}

// ---------------------------------------------------------------------------
// 2-col x 8-edge smem-broadcast GEMM chunk:
//   acc[col*8+e] += m[e][r] * W[r][c0+col]
// W row-major [ROWS x 128], loaded as float2 at column c0 (c0 even).
// m rows have STRIDE floats.
// ---------------------------------------------------------------------------
template<int ROWS, int STRIDE>
__device__ __forceinline__ void gemm2x8(float acc[16], const float* __restrict__ W,
                                        const float* m, int c0)
{
    float2 w0 = *(const float2*)(W + 0*128 + c0);
    float2 w1 = *(const float2*)(W + 1*128 + c0);
    float2 w2 = *(const float2*)(W + 2*128 + c0);
    float2 w3 = *(const float2*)(W + 3*128 + c0);
    #pragma unroll 1
    for (int r = 0; r < ROWS; r += 4) {
        float2 n0 = {0.f,0.f}, n1 = {0.f,0.f}, n2 = {0.f,0.f}, n3 = {0.f,0.f};
        if (r + 4 < ROWS) {
            const float* Wn = W + (r+4)*128 + c0;
            n0 = *(const float2*)(Wn);
            n1 = *(const float2*)(Wn + 128);
            n2 = *(const float2*)(Wn + 256);
            n3 = *(const float2*)(Wn + 384);
        }
        #pragma unroll
        for (int e = 0; e < 8; ++e) {
            float4 v = *(const float4*)(m + e*STRIDE + r);
            acc[e]   = fmaf(v.x, w0.x, acc[e]);
            acc[8+e] = fmaf(v.x, w0.y, acc[8+e]);
            acc[e]   = fmaf(v.y, w1.x, acc[e]);
            acc[8+e] = fmaf(v.y, w1.y, acc[8+e]);
            acc[e]   = fmaf(v.z, w2.x, acc[e]);
            acc[8+e] = fmaf(v.z, w2.y, acc[8+e]);
            acc[e]   = fmaf(v.w, w3.x, acc[e]);
            acc[8+e] = fmaf(v.w, w3.y, acc[8+e]);
        }
        w0=n0; w1=n1; w2=n2; w3=n3;
    }
}

__device__ __forceinline__ float warp_sum(float v) {
    #pragma unroll
    for (int o = 16; o; o >>= 1) v += __shfl_xor_sync(0xffffffffu, v, o);
    return v;
}

// smem layout (floats)
#define SM_BUF   0         // 32*128 = 4096 : h_E stage -> nbr_hV stage -> m2
#define SM_M1    4096      // 4096
#define SM_GEO   8192      // 32*40 = 1280
#define SM_HV    9472      // 128
#define SM_S1    9600      // 128
#define SM_HS    9728      // 128
#define SM_D1    9856      // 512
#define SM_RN    10368     // 12
#define SM_TN    10380     // 4
#define SM_PGN   10384     // 24
#define SM_MA    10408     // 32
#define SM_RED   10440     // 8
#define SM_PD    10448     // 512 (4 groups x 128)
#define SM_EIX   10960     // 32 (ints)
#define SM_FLOATS 10992
#define SMEM_BYTES (SM_FLOATS*4)

// ---------------------------------------------------------------------------
// Kernel 2: per-node edge messages + MLP + reduce + LN + dense + LN
// 256 threads: group g = t>>6 (4 groups) owns edges [g*8, g*8+8);
// column pair c0 = (t&63)*2.
// ---------------------------------------------------------------------------
__global__ void __launch_bounds__(256, 4)
msg_kernel(const float* __restrict__ hV_g, const float* __restrict__ hE_g,
           const float* __restrict__ maskV_g, const float* __restrict__ maskA_g,
           const float* __restrict__ Wm1,
           const float* __restrict__ Wm2, const float* __restrict__ bm2,
           const float* __restrict__ Wm3, const float* __restrict__ bm3,
           const float* __restrict__ g1, const float* __restrict__ be1,
           const float* __restrict__ Wd1, const float* __restrict__ bd1,
           const float* __restrict__ Wd2, const float* __restrict__ bd2,
           const float* __restrict__ g2, const float* __restrict__ be2,
           const int* __restrict__ Eidx, float* __restrict__ out)
{
    extern __shared__ float sm[];
    float* buf = sm + SM_BUF;
    float* m1  = sm + SM_M1;
    float* geo = sm + SM_GEO;
    float* hv  = sm + SM_HV;
    float* s1  = sm + SM_S1;
    float* hs  = sm + SM_HS;
    float* d1s = sm + SM_D1;
    float* Rn  = sm + SM_RN;
    float* tn  = sm + SM_TN;
    float* pgn = sm + SM_PGN;
    float* mA  = sm + SM_MA;
    float* red = sm + SM_RED;
    float* pd  = sm + SM_PD;
    int*   eix = (int*)(sm + SM_EIX);

    int node = blockIdx.x;
    int batch = node / NN;
    int t = threadIdx.x;
    int w = t >> 5, lane = t & 31;
    int g = t >> 6;           // 4 edge groups
    int c0 = (t & 63) * 2;    // column pair
    int e0 = g * 8;

    if (t < 128) {
        hv[t] = hV_g[(size_t)node*DD + t];
        s1[t] = g_s1[(size_t)node*HH + t];
    } else {
        int u = t - 128;
        if (u < 24) pgn[u] = g_pg[(size_t)node*24 + u];
        else if (u < 33) Rn[u-24] = g_R[(size_t)node*9 + (u-24)];
        else if (u < 36) tn[u-33] = g_t[(size_t)node*3 + (u-33)];
        else if (u >= 64 && u < 96) mA[u-64] = maskA_g[(size_t)node*KK + (u-64)];
        else if (u >= 96 && u < 128) eix[u-96] = Eidx[(size_t)node*KK + (u-96)];
    }
    __syncthreads();

    // ---------------- phase 1: stage h_E (coalesced copy) ----------------
    {
        const float4* src = (const float4*)(hE_g + (size_t)node*KK*DD);
        float4* dst = (float4*)buf;
        #pragma unroll
        for (int i = 0; i < 4; ++i) dst[t + i*256] = src[t + i*256];
    }
    // geometry rows while staging: warp w handles edges w, w+8, w+16, w+24
    #pragma unroll
    for (int ii = 0; ii < 4; ++ii) {
        int e = w + ii*8;
        if (lane < 8) {
            int p = lane;
            int j = eix[e];
            const float* qg = g_pg + (size_t)(batch*NN + j)*24 + p*3;
            float q0 = qg[0], q1 = qg[1], q2 = qg[2];
            float d0 = pgn[p*3+0]-q0, d1 = pgn[p*3+1]-q1, d2 = pgn[p*3+2]-q2;
            float cc0 = q0 - tn[0], cc1 = q1 - tn[1], cc2 = q2 - tn[2];
            float l0 = Rn[0]*cc0 + Rn[3]*cc1 + Rn[6]*cc2;
            float l1 = Rn[1]*cc0 + Rn[4]*cc1 + Rn[7]*cc2;
            float l2 = Rn[2]*cc0 + Rn[5]*cc1 + Rn[8]*cc2;
            float* row = geo + e*40;
            row[p*3+0] = l0; row[p*3+1] = l1; row[p*3+2] = l2;
            row[24+p] = sqrtf(l0*l0+l1*l1+l2*l2 + 1e-8f);
            row[32+p] = sqrtf(d0*d0+d1*d1+d2*d2 + 1e-8f);
        }
    }
    __syncthreads();

    // ---------------- layer 1 ----------------
    float acc[16];
    {
        float sa = s1[c0], sb = s1[c0+1];
        #pragma unroll
        for (int e = 0; e < 8; ++e) { acc[e] = sa; acc[8+e] = sb; }
    }
    gemm2x8<128,128>(acc, Wm1 + 128*HH, buf + e0*128, c0);   // h_E rows 128..255
    __syncthreads();

    // ---------------- phase 2: stage nbr_hV (gather) ----------------
    #pragma unroll
    for (int ii = 0; ii < 4; ++ii) {
        int e = w + ii*8;
        int j = eix[e];
        const float4* src = (const float4*)(hV_g + (size_t)(batch*NN + j)*DD);
        ((float4*)(buf + e*128))[lane] = src[lane];
    }
    __syncthreads();

    gemm2x8<128,128>(acc, Wm1 + 256*HH, buf + e0*128, c0);   // nbr_hV rows 256..383
    gemm2x8<40,40>  (acc, Wm1 + 416*HH, geo + e0*40,  c0);   // geometry rows 416..455
    #pragma unroll
    for (int e = 0; e < 8; ++e) {
        float2 v = { fmaxf(acc[e], 0.f), fmaxf(acc[8+e], 0.f) };
        *(float2*)(m1 + (e0+e)*128 + c0) = v;
    }
    __syncthreads();

    // ---------------- layer 2 (writes m2 = buf) ----------------
    {
        float ba = bm2[c0], bb = bm2[c0+1];
        #pragma unroll
        for (int e = 0; e < 8; ++e) { acc[e] = ba; acc[8+e] = bb; }
    }
    gemm2x8<128,128>(acc, Wm2, m1 + e0*128, c0);
    __syncthreads();   // all reads of buf (stage-2) done before overwrite
    #pragma unroll
    for (int e = 0; e < 8; ++e) {
        float2 v = { fmaxf(acc[e], 0.f), fmaxf(acc[8+e], 0.f) };
        *(float2*)(buf + (e0+e)*128 + c0) = v;
    }
    __syncthreads();

    // ---------------- layer 3 (no relu) ----------------
    {
        float ba = bm3[c0], bb = bm3[c0+1];
        #pragma unroll
        for (int e = 0; e < 8; ++e) { acc[e] = ba; acc[8+e] = bb; }
    }
    gemm2x8<128,128>(acc, Wm3, buf + e0*128, c0);

    // mask + partial mean over this group's edges
    {
        float nma = 0.f, nmb = 0.f;
        #pragma unroll
        for (int e = 0; e < 8; ++e) {
            float mk = mA[e0+e];
            nma = fmaf(acc[e],   mk, nma);
            nmb = fmaf(acc[8+e], mk, nmb);
        }
        pd[g*128 + c0]   = nma;
        pd[g*128 + c0+1] = nmb;
    }
    __syncthreads();

    // ---------------- LN1(h_V + node_m)  (threads 0..127) ----------------
    float x = 0.f, dx = 0.f;
    if (t < 128) {
        int c = t;
        float nm = (pd[c] + pd[128+c] + pd[256+c] + pd[384+c]) * (1.0f/KK);
        x = hv[c] + nm;
        float sA = warp_sum(x);
        if (!lane) red[w] = sA;
    }
    __syncthreads();
    if (t < 128) {
        float mu = (red[0]+red[1]+red[2]+red[3]) * (1.0f/HH);
        dx = x - mu;
        float sB = warp_sum(dx*dx);
        __syncwarp();
        if (!lane) red[w+4] = sB;
    }
    __syncthreads();
    if (t < 128) {
        float var = (red[4]+red[5]+red[6]+red[7]) * (1.0f/HH);
        hs[t] = dx * rsqrtf(var + 1e-5f) * g1[t] + be1[t];
    }
    __syncthreads();

    // ---------------- dense1: 128 -> 512 relu (each thread 2 cols) ----------------
    {
        int d0 = t, d1 = t + 256;
        float a0 = bd1[d0], a1 = bd1[d1];
        #pragma unroll 4
        for (int r = 0; r < HH; ++r) {
            float hr = hs[r];
            a0 = fmaf(hr, Wd1[r*512 + d0], a0);
            a1 = fmaf(hr, Wd1[r*512 + d1], a1);
        }
        d1s[d0] = fmaxf(a0, 0.f);
        d1s[d1] = fmaxf(a1, 0.f);
    }
    __syncthreads();

    // ---------------- dense2: 512 -> 128, row-split across 4 groups ----------------
    {
        float oa = 0.f, ob = 0.f;
        const float* dbase = d1s + g*128;
        const float* Wbase = Wd2 + (size_t)g*128*128 + c0;
        #pragma unroll 2
        for (int r = 0; r < 128; r += 4) {
            float4 dv = *(const float4*)(dbase + r);
            float2 q0 = *(const float2*)(Wbase + (r+0)*128);
            float2 q1 = *(const float2*)(Wbase + (r+1)*128);
            float2 q2 = *(const float2*)(Wbase + (r+2)*128);
            float2 q3 = *(const float2*)(Wbase + (r+3)*128);
            oa = fmaf(dv.x, q0.x, oa); ob = fmaf(dv.x, q0.y, ob);
            oa = fmaf(dv.y, q1.x, oa); ob = fmaf(dv.y, q1.y, ob);
            oa = fmaf(dv.z, q2.x, oa); ob = fmaf(dv.z, q2.y, ob);
            oa = fmaf(dv.w, q3.x, oa); ob = fmaf(dv.w, q3.y, ob);
        }
        pd[g*128 + c0]   = oa;
        pd[g*128 + c0+1] = ob;
    }
    __syncthreads();

    // ---------------- LN2(h + dense), mask_V  (threads 0..127) ----------------
    float x2 = 0.f, dx2 = 0.f;
    if (t < 128) {
        int c = t;
        x2 = hs[c] + bd2[c] + pd[c] + pd[128+c] + pd[256+c] + pd[384+c];
        float sA = warp_sum(x2);
        if (!lane) red[w] = sA;
    }
    __syncthreads();
    if (t < 128) {
        float mu2 = (red[0]+red[1]+red[2]+red[3]) * (1.0f/HH);
        dx2 = x2 - mu2;
        float sB = warp_sum(dx2*dx2);
        __syncwarp();
        if (!lane) red[w+4] = sB;
    }
    __syncthreads();
    if (t < 128) {
        float var2 = (red[4]+red[5]+red[6]+red[7]) * (1.0f/HH);
        float y = (dx2 * rsqrtf(var2 + 1e-5f) * g2[t] + be2[t]) * maskV_g[node];
        out[(size_t)node*HH + t] = y;
    }
}

// ---------------------------------------------------------------------------
extern "C" void kernel_launch(void* const* d_in, const int* in_sizes, int n_in,
                              void* d_out, int out_size)
{
    const float* hV    = (const float*)d_in[0];
    const float* hE    = (const float*)d_in[1];
    const float* X     = (const float*)d_in[2];
    const float* maskV = (const float*)d_in[3];
    const float* maskA = (const float*)d_in[4];
    const float* Wp    = (const float*)d_in[5];
    const float* bp    = (const float*)d_in[6];
    const float* Wm1   = (const float*)d_in[7];
    const float* bm1   = (const float*)d_in[8];
    const float* Wm2   = (const float*)d_in[9];
    const float* bm2   = (const float*)d_in[10];
    const float* Wm3   = (const float*)d_in[11];
    const float* bm3   = (const float*)d_in[12];
    const float* g1    = (const float*)d_in[13];
    const float* be1   = (const float*)d_in[14];
    const float* Wd1   = (const float*)d_in[15];
    const float* bd1   = (const float*)d_in[16];
    const float* Wd2   = (const float*)d_in[17];
    const float* bd2   = (const float*)d_in[18];
    const float* g2    = (const float*)d_in[19];
    const float* be2   = (const float*)d_in[20];
    const int*   Eidx  = (const int*)d_in[21];
    float* out = (float*)d_out;

    node_prep_kernel<<<NODES, 128>>>(hV, X, Wp, bp, Wm1, bm1);
    msg_kernel<<<NODES, 256, SMEM_BYTES>>>(hV, hE, maskV, maskA, Wm1,
                                           Wm2, bm2, Wm3, bm3, g1, be1,
                                           Wd1, bd1, Wd2, bd2, g2, be2,
                                           Eidx, out);

    // second output: h_E passthrough
    long long hcount = (long long)NODES * HH;
    if ((long long)out_size > hcount) {
        long long n = (long long)out_size - hcount;
        long long emax = (long long)BB*NN*KK*DD;
        if (n > emax) n = emax;
        cudaMemcpyAsync(out + hcount, hE, (size_t)n * sizeof(float),
                        cudaMemcpyDeviceToDevice);
    }
}

// round 4
// speedup vs baseline: 1.9041x; 1.3442x over previous
#include <cuda_runtime.h>
#include <math.h>
#include <stdint.h>

#define BB 8
#define NN 512
#define KK 32
#define DD 128
#define HH 128
#define PP 8
#define NODES (BB*NN)

// Scratch (allocation-free rule: __device__ globals)
__device__ float g_pg[NODES*PP*3];   // global points per node
__device__ float g_R[NODES*9];       // frames
__device__ float g_t[NODES*3];       // translations
__device__ float g_s1[NODES*HH];     // static part of layer-1 pre-activation (incl bias)

// tf32-pre-rounded weights
__device__ float g_w1e[256*128];     // Wm1 rows 128..383 (h_E + nbr_hV)
__device__ float g_w1g[40*128];      // Wm1 rows 416..455 (geometry)
__device__ float g_w2[128*128];
__device__ float g_w3[128*128];

__device__ __forceinline__ uint32_t f2tf32(float f) {
    uint32_t o;
    asm("cvt.rna.tf32.f32 %0, %1;" : "=r"(o) : "f"(f));
    return o;
}

// ---------------------------------------------------------------------------
// Kernel 0: pre-round weights to tf32
// ---------------------------------------------------------------------------
__global__ void weight_prep(const float* __restrict__ Wm1,
                            const float* __restrict__ Wm2,
                            const float* __restrict__ Wm3)
{
    int i = blockIdx.x * blockDim.x + threadIdx.x;
    if (i < 256*128) g_w1e[i] = __uint_as_float(f2tf32(Wm1[128*128 + i]));
    if (i < 40*128)  g_w1g[i] = __uint_as_float(f2tf32(Wm1[416*128 + i]));
    if (i < 128*128) {
        g_w2[i] = __uint_as_float(f2tf32(Wm2[i]));
        g_w3[i] = __uint_as_float(f2tf32(Wm3[i]));
    }
}

// ---------------------------------------------------------------------------
// Kernel 1: per-node frame, local/global points, static layer-1 contribution
// ---------------------------------------------------------------------------
__global__ void node_prep_kernel(const float* __restrict__ hV_g,
                                 const float* __restrict__ X,
                                 const float* __restrict__ Wp,
                                 const float* __restrict__ bp,
                                 const float* __restrict__ Wm1,
                                 const float* __restrict__ bm1)
{
    int node = blockIdx.x;
    int t = threadIdx.x;
    __shared__ float hv[DD];
    __shared__ float pl[24];
    __shared__ float plnorm[8];
    __shared__ float Rn[9];
    __shared__ float tn[3];

    hv[t] = hV_g[(size_t)node*DD + t];
    __syncthreads();

    if (t == 0) {
        const float* x = X + (size_t)node*9;
        float Xn0=x[0],Xn1=x[1],Xn2=x[2];
        float Xa0=x[3],Xa1=x[4],Xa2=x[5];
        float Xc0=x[6],Xc1=x[7],Xc2=x[8];
        float v10=Xc0-Xa0, v11=Xc1-Xa1, v12=Xc2-Xa2;
        float v20=Xn0-Xa0, v21=Xn1-Xa1, v22=Xn2-Xa2;
        float inv1 = rsqrtf(v10*v10+v11*v11+v12*v12+1e-8f);
        float e10=v10*inv1, e11=v11*inv1, e12=v12*inv1;
        float dp = e10*v20+e11*v21+e12*v22;
        float u20=v20-e10*dp, u21=v21-e11*dp, u22=v22-e12*dp;
        float inv2 = rsqrtf(u20*u20+u21*u21+u22*u22+1e-8f);
        float e20=u20*inv2, e21=u21*inv2, e22=u22*inv2;
        float e30=e11*e22-e12*e21;
        float e31=e12*e20-e10*e22;
        float e32=e10*e21-e11*e20;
        Rn[0]=e10; Rn[1]=e20; Rn[2]=e30;
        Rn[3]=e11; Rn[4]=e21; Rn[5]=e31;
        Rn[6]=e12; Rn[7]=e22; Rn[8]=e32;
        tn[0]=Xa0*0.1f; tn[1]=Xa1*0.1f; tn[2]=Xa2*0.1f;
    }
    if (t < 24) {
        float acc = bp[t];
        #pragma unroll 8
        for (int d = 0; d < DD; ++d) acc += hv[d] * Wp[d*24 + t];
        pl[t] = acc;
    }
    __syncthreads();

    if (t < 8) {
        float a=pl[t*3+0], b=pl[t*3+1], c=pl[t*3+2];
        plnorm[t] = sqrtf(a*a+b*b+c*c + 1e-8f);
    }
    if (t < 24) {
        int p = t/3, i = t%3;
        float pg = tn[i] + Rn[i*3+0]*pl[p*3+0] + Rn[i*3+1]*pl[p*3+1] + Rn[i*3+2]*pl[p*3+2];
        g_pg[(size_t)node*24 + t] = pg;
    }
    if (t < 9) g_R[(size_t)node*9 + t] = Rn[t];
    if (t < 3) g_t[(size_t)node*3 + t] = tn[t];
    __syncthreads();

    // static layer-1 contribution (kept fully fp32 for accuracy)
    float s = bm1[t];
    #pragma unroll 4
    for (int d = 0; d < DD; ++d) s += hv[d] * Wm1[d*HH + t];
    #pragma unroll
    for (int j = 0; j < 24; ++j) s += pl[j] * Wm1[(384+j)*HH + t];
    #pragma unroll
    for (int p = 0; p < 8; ++p) s += plnorm[p] * Wm1[(408+p)*HH + t];
    g_s1[(size_t)node*HH + t] = s;
}

// ---------------------------------------------------------------------------
// tf32 m16n8k8 mma block: acc[nt][0..3] over KSTEPS k-chunks.
// act: smem, row stride S floats (values pre-rounded to tf32 bits).
// W: global, row-major [K x 128], pre-rounded to tf32.
// Warp handles rows [mh*16, mh*16+16), cols [ng*32, ng*32+32).
// ---------------------------------------------------------------------------
template<int KSTEPS, int S>
__device__ __forceinline__ void mma_block(float acc[4][4], const float* act,
                                          const float* __restrict__ W,
                                          int lane, int mh, int ng)
{
    int gid = lane >> 2, q = lane & 3;
    const float* r0 = act + (mh*16 + gid) * S;
    const float* r1 = r0 + 8*S;
    #pragma unroll 2
    for (int ks = 0; ks < KSTEPS; ++ks) {
        int k0 = ks*8;
        uint32_t a0 = __float_as_uint(r0[k0+q]);
        uint32_t a1 = __float_as_uint(r1[k0+q]);
        uint32_t a2 = __float_as_uint(r0[k0+q+4]);
        uint32_t a3 = __float_as_uint(r1[k0+q+4]);
        #pragma unroll
        for (int nt = 0; nt < 4; ++nt) {
            int n0 = ng*32 + nt*8 + gid;
            uint32_t b0 = __float_as_uint(W[(k0+q)*128 + n0]);
            uint32_t b1 = __float_as_uint(W[(k0+q+4)*128 + n0]);
            asm volatile(
                "mma.sync.aligned.m16n8k8.row.col.f32.tf32.tf32.f32 "
                "{%0,%1,%2,%3},{%4,%5,%6,%7},{%8,%9},{%0,%1,%2,%3};"
                : "+f"(acc[nt][0]), "+f"(acc[nt][1]), "+f"(acc[nt][2]), "+f"(acc[nt][3])
                : "r"(a0), "r"(a1), "r"(a2), "r"(a3), "r"(b0), "r"(b1));
        }
    }
}

__device__ __forceinline__ float warp_sum(float v) {
    #pragma unroll
    for (int o = 16; o; o >>= 1) v += __shfl_xor_sync(0xffffffffu, v, o);
    return v;
}

// smem layout (floats)
#define ASTRIDE 132
#define GSTRIDE 44
#define SM_BUFA  0          // 32*132 = 4224
#define SM_BUFB  4224       // 4224
#define SM_GEO   8448       // 32*44 = 1408
#define SM_HV    9856       // 128
#define SM_S1    9984       // 128
#define SM_HS    10112      // 128
#define SM_D1    10240      // 512
#define SM_RN    10752      // 12
#define SM_TN    10764      // 4
#define SM_PGN   10768      // 24
#define SM_MA    10792      // 32
#define SM_RED   10824      // 8
#define SM_PD    10832      // 512
#define SM_EIX   11344      // 32 (ints)
#define SM_FLOATS 11376
#define SMEM_BYTES (SM_FLOATS*4)

// ---------------------------------------------------------------------------
// Kernel 2: per-node edge messages (tf32 MMA) + reduce + LN + dense + LN
// 256 threads, 8 warps: warp w -> mh = w&1 (16 edges), ng = w>>1 (32 cols).
// ---------------------------------------------------------------------------
__global__ void __launch_bounds__(256, 4)
msg_kernel(const float* __restrict__ hV_g, const float* __restrict__ hE_g,
           const float* __restrict__ maskV_g, const float* __restrict__ maskA_g,
           const float* __restrict__ bm2, const float* __restrict__ bm3,
           const float* __restrict__ g1, const float* __restrict__ be1,
           const float* __restrict__ Wd1, const float* __restrict__ bd1,
           const float* __restrict__ Wd2, const float* __restrict__ bd2,
           const float* __restrict__ g2, const float* __restrict__ be2,
           const int* __restrict__ Eidx, float* __restrict__ out)
{
    extern __shared__ float sm[];
    float* bufA = sm + SM_BUFA;
    float* bufB = sm + SM_BUFB;
    float* geo = sm + SM_GEO;
    float* hv  = sm + SM_HV;
    float* s1  = sm + SM_S1;
    float* hs  = sm + SM_HS;
    float* d1s = sm + SM_D1;
    float* Rn  = sm + SM_RN;
    float* tn  = sm + SM_TN;
    float* pgn = sm + SM_PGN;
    float* mA  = sm + SM_MA;
    float* red = sm + SM_RED;
    float* pd  = sm + SM_PD;
    int*   eix = (int*)(sm + SM_EIX);

    int node = blockIdx.x;
    int batch = node / NN;
    int t = threadIdx.x;
    int w = t >> 5, lane = t & 31;
    int mh = w & 1, ng = w >> 1;
    int gid = lane >> 2, q = lane & 3;

    if (t < 128) {
        hv[t] = hV_g[(size_t)node*DD + t];
        s1[t] = g_s1[(size_t)node*HH + t];
    } else {
        int u = t - 128;
        if (u < 24) pgn[u] = g_pg[(size_t)node*24 + u];
        else if (u < 33) Rn[u-24] = g_R[(size_t)node*9 + (u-24)];
        else if (u < 36) tn[u-33] = g_t[(size_t)node*3 + (u-33)];
        else if (u >= 64 && u < 96) mA[u-64] = maskA_g[(size_t)node*KK + (u-64)];
        else if (u >= 96 && u < 128) eix[u-96] = Eidx[(size_t)node*KK + (u-96)];
    }
    __syncthreads();

    // ---------------- phase 1: stage h_E into bufA (tf32-rounded) --------
    {
        const float4* src = (const float4*)(hE_g + (size_t)node*KK*DD);
        #pragma unroll
        for (int i = 0; i < 4; ++i) {
            int f4 = t + i*256;          // float4 index, 0..1023
            float4 v = src[f4];
            int e = f4 >> 5, c = (f4 & 31) * 4;
            float4 o;
            o.x = __uint_as_float(f2tf32(v.x));
            o.y = __uint_as_float(f2tf32(v.y));
            o.z = __uint_as_float(f2tf32(v.z));
            o.w = __uint_as_float(f2tf32(v.w));
            *(float4*)(bufA + e*ASTRIDE + c) = o;
        }
    }
    // geometry rows while staging: warp w handles edges w, w+8, w+16, w+24
    #pragma unroll
    for (int ii = 0; ii < 4; ++ii) {
        int e = w + ii*8;
        if (lane < 8) {
            int p = lane;
            int j = eix[e];
            const float* qg = g_pg + (size_t)(batch*NN + j)*24 + p*3;
            float q0 = qg[0], q1 = qg[1], q2 = qg[2];
            float d0 = pgn[p*3+0]-q0, d1 = pgn[p*3+1]-q1, d2 = pgn[p*3+2]-q2;
            float cc0 = q0 - tn[0], cc1 = q1 - tn[1], cc2 = q2 - tn[2];
            float l0 = Rn[0]*cc0 + Rn[3]*cc1 + Rn[6]*cc2;
            float l1 = Rn[1]*cc0 + Rn[4]*cc1 + Rn[7]*cc2;
            float l2 = Rn[2]*cc0 + Rn[5]*cc1 + Rn[8]*cc2;
            float* row = geo + e*GSTRIDE;
            row[p*3+0] = __uint_as_float(f2tf32(l0));
            row[p*3+1] = __uint_as_float(f2tf32(l1));
            row[p*3+2] = __uint_as_float(f2tf32(l2));
            row[24+p] = __uint_as_float(f2tf32(sqrtf(l0*l0+l1*l1+l2*l2 + 1e-8f)));
            row[32+p] = __uint_as_float(f2tf32(sqrtf(d0*d0+d1*d1+d2*d2 + 1e-8f)));
            row[40] = 0.f; row[41] = 0.f; row[42] = 0.f; row[43] = 0.f; // pad
        }
    }
    __syncthreads();

    // ---------------- layer 1, phase A: h_E rows ----------------
    float acc[4][4];
    #pragma unroll
    for (int nt = 0; nt < 4; ++nt)
        #pragma unroll
        for (int i = 0; i < 4; ++i) acc[nt][i] = 0.f;

    mma_block<16, ASTRIDE>(acc, bufA, g_w1e, lane, mh, ng);
    __syncthreads();

    // ---------------- stage nbr_hV into bufA (gather, tf32) -------------
    #pragma unroll
    for (int ii = 0; ii < 4; ++ii) {
        int e = w + ii*8;
        int j = eix[e];
        const float4* src = (const float4*)(hV_g + (size_t)(batch*NN + j)*DD);
        float4 v = src[lane];
        float4 o;
        o.x = __uint_as_float(f2tf32(v.x));
        o.y = __uint_as_float(f2tf32(v.y));
        o.z = __uint_as_float(f2tf32(v.z));
        o.w = __uint_as_float(f2tf32(v.w));
        *(float4*)(bufA + e*ASTRIDE + lane*4) = o;
    }
    __syncthreads();

    // ---------------- layer 1, phase B: nbr_hV + geometry ----------------
    mma_block<16, ASTRIDE>(acc, bufA, g_w1e + 128*128, lane, mh, ng);
    mma_block<5,  GSTRIDE>(acc, geo,  g_w1g, lane, mh, ng);

    // add static part + relu, store tf32 to bufB
    {
        int e0r = mh*16 + gid;
        #pragma unroll
        for (int nt = 0; nt < 4; ++nt) {
            int cb = ng*32 + nt*8 + 2*q;
            float sa = s1[cb], sb = s1[cb+1];
            uint2 u0, u1;
            u0.x = f2tf32(fmaxf(acc[nt][0] + sa, 0.f));
            u0.y = f2tf32(fmaxf(acc[nt][1] + sb, 0.f));
            u1.x = f2tf32(fmaxf(acc[nt][2] + sa, 0.f));
            u1.y = f2tf32(fmaxf(acc[nt][3] + sb, 0.f));
            *(uint2*)(bufB + e0r*ASTRIDE + cb) = u0;
            *(uint2*)(bufB + (e0r+8)*ASTRIDE + cb) = u1;
        }
    }
    __syncthreads();

    // ---------------- layer 2 ----------------
    #pragma unroll
    for (int nt = 0; nt < 4; ++nt)
        #pragma unroll
        for (int i = 0; i < 4; ++i) acc[nt][i] = 0.f;
    mma_block<16, ASTRIDE>(acc, bufB, g_w2, lane, mh, ng);
    {
        int e0r = mh*16 + gid;
        #pragma unroll
        for (int nt = 0; nt < 4; ++nt) {
            int cb = ng*32 + nt*8 + 2*q;
            float ba = bm2[cb], bb = bm2[cb+1];
            uint2 u0, u1;
            u0.x = f2tf32(fmaxf(acc[nt][0] + ba, 0.f));
            u0.y = f2tf32(fmaxf(acc[nt][1] + bb, 0.f));
            u1.x = f2tf32(fmaxf(acc[nt][2] + ba, 0.f));
            u1.y = f2tf32(fmaxf(acc[nt][3] + bb, 0.f));
            *(uint2*)(bufA + e0r*ASTRIDE + cb) = u0;
            *(uint2*)(bufA + (e0r+8)*ASTRIDE + cb) = u1;
        }
    }
    __syncthreads();

    // ---------------- layer 3 (no relu) + masked mean ----------------
    #pragma unroll
    for (int nt = 0; nt < 4; ++nt)
        #pragma unroll
        for (int i = 0; i < 4; ++i) acc[nt][i] = 0.f;
    mma_block<16, ASTRIDE>(acc, bufA, g_w3, lane, mh, ng);
    {
        float mk0 = mA[mh*16 + gid], mk1 = mA[mh*16 + gid + 8];
        #pragma unroll
        for (int nt = 0; nt < 4; ++nt) {
            int cb = ng*32 + nt*8 + 2*q;
            float ba = bm3[cb], bb = bm3[cb+1];
            float ve = (acc[nt][0] + ba)*mk0 + (acc[nt][2] + ba)*mk1;
            float vo = (acc[nt][1] + bb)*mk0 + (acc[nt][3] + bb)*mk1;
            #pragma unroll
            for (int o = 4; o <= 16; o <<= 1) {
                ve += __shfl_xor_sync(0xffffffffu, ve, o);
                vo += __shfl_xor_sync(0xffffffffu, vo, o);
            }
            if (gid == 0) {
                pd[mh*128 + cb] = ve;
                pd[mh*128 + cb + 1] = vo;
            }
        }
    }
    __syncthreads();

    // ---------------- LN1(h_V + node_m)  (threads 0..127) ----------------
    float x = 0.f, dx = 0.f;
    if (t < 128) {
        float nm = (pd[t] + pd[128+t]) * (1.0f/KK);
        x = hv[t] + nm;
        float sA = warp_sum(x);
        if (!lane) red[w] = sA;
    }
    __syncthreads();
    if (t < 128) {
        float mu = (red[0]+red[1]+red[2]+red[3]) * (1.0f/HH);
        dx = x - mu;
        float sB = warp_sum(dx*dx);
        __syncwarp();
        if (!lane) red[w+4] = sB;
    }
    __syncthreads();
    if (t < 128) {
        float var = (red[4]+red[5]+red[6]+red[7]) * (1.0f/HH);
        hs[t] = dx * rsqrtf(var + 1e-5f) * g1[t] + be1[t];
    }
    __syncthreads();

    // ---------------- dense1: 128 -> 512 relu (each thread 2 cols) -------
    {
        int c0 = t, c1 = t + 256;
        float a0 = bd1[c0], a1 = bd1[c1];
        #pragma unroll 4
        for (int r = 0; r < HH; ++r) {
            float hr = hs[r];
            a0 = fmaf(hr, Wd1[r*512 + c0], a0);
            a1 = fmaf(hr, Wd1[r*512 + c1], a1);
        }
        d1s[c0] = fmaxf(a0, 0.f);
        d1s[c1] = fmaxf(a1, 0.f);
    }
    __syncthreads();

    // ---------------- dense2: 512 -> 128, row-split across 4 groups ------
    {
        int gg = t >> 6;
        int c0 = (t & 63) * 2;
        float oa = 0.f, ob = 0.f;
        const float* dbase = d1s + gg*128;
        const float* Wbase = Wd2 + (size_t)gg*128*128 + c0;
        #pragma unroll 2
        for (int r = 0; r < 128; r += 4) {
            float4 dv = *(const float4*)(dbase + r);
            float2 q0 = *(const float2*)(Wbase + (r+0)*128);
            float2 q1 = *(const float2*)(Wbase + (r+1)*128);
            float2 q2 = *(const float2*)(Wbase + (r+2)*128);
            float2 q3 = *(const float2*)(Wbase + (r+3)*128);
            oa = fmaf(dv.x, q0.x, oa); ob = fmaf(dv.x, q0.y, ob);
            oa = fmaf(dv.y, q1.x, oa); ob = fmaf(dv.y, q1.y, ob);
            oa = fmaf(dv.z, q2.x, oa); ob = fmaf(dv.z, q2.y, ob);
            oa = fmaf(dv.w, q3.x, oa); ob = fmaf(dv.w, q3.y, ob);
        }
        pd[gg*128 + c0]   = oa;
        pd[gg*128 + c0+1] = ob;
    }
    __syncthreads();

    // ---------------- LN2(h + dense), mask_V  (threads 0..127) -----------
    float x2 = 0.f, dx2 = 0.f;
    if (t < 128) {
        x2 = hs[t] + bd2[t] + pd[t] + pd[128+t] + pd[256+t] + pd[384+t];
        float sA = warp_sum(x2);
        if (!lane) red[w] = sA;
    }
    __syncthreads();
    if (t < 128) {
        float mu2 = (red[0]+red[1]+red[2]+red[3]) * (1.0f/HH);
        dx2 = x2 - mu2;
        float sB = warp_sum(dx2*dx2);
        __syncwarp();
        if (!lane) red[w+4] = sB;
    }
    __syncthreads();
    if (t < 128) {
        float var2 = (red[4]+red[5]+red[6]+red[7]) * (1.0f/HH);
        float y = (dx2 * rsqrtf(var2 + 1e-5f) * g2[t] + be2[t]) * maskV_g[node];
        out[(size_t)node*HH + t] = y;
    }
}

// ---------------------------------------------------------------------------
extern "C" void kernel_launch(void* const* d_in, const int* in_sizes, int n_in,
                              void* d_out, int out_size)
{
    const float* hV    = (const float*)d_in[0];
    const float* hE    = (const float*)d_in[1];
    const float* X     = (const float*)d_in[2];
    const float* maskV = (const float*)d_in[3];
    const float* maskA = (const float*)d_in[4];
    const float* Wp    = (const float*)d_in[5];
    const float* bp    = (const float*)d_in[6];
    const float* Wm1   = (const float*)d_in[7];
    const float* bm1   = (const float*)d_in[8];
    const float* Wm2   = (const float*)d_in[9];
    const float* bm2   = (const float*)d_in[10];
    const float* Wm3   = (const float*)d_in[11];
    const float* bm3   = (const float*)d_in[12];
    const float* g1    = (const float*)d_in[13];
    const float* be1   = (const float*)d_in[14];
    const float* Wd1   = (const float*)d_in[15];
    const float* bd1   = (const float*)d_in[16];
    const float* Wd2   = (const float*)d_in[17];
    const float* bd2   = (const float*)d_in[18];
    const float* g2    = (const float*)d_in[19];
    const float* be2   = (const float*)d_in[20];
    const int*   Eidx  = (const int*)d_in[21];
    float* out = (float*)d_out;

    weight_prep<<<128, 256>>>(Wm1, Wm2, Wm3);
    node_prep_kernel<<<NODES, 128>>>(hV, X, Wp, bp, Wm1, bm1);
    msg_kernel<<<NODES, 256, SMEM_BYTES>>>(hV, hE, maskV, maskA,
                                           bm2, bm3, g1, be1,
                                           Wd1, bd1, Wd2, bd2, g2, be2,
                                           Eidx, out);

    // second output: h_E passthrough
    long long hcount = (long long)NODES * HH;
    if ((long long)out_size > hcount) {
        long long n = (long long)out_size - hcount;
        long long emax = (long long)BB*NN*KK*DD;
        if (n > emax) n = emax;
        cudaMemcpyAsync(out + hcount, hE, (size_t)n * sizeof(float),
                        cudaMemcpyDeviceToDevice);
    }
}

// round 5
// speedup vs baseline: 3.0983x; 1.6271x over previous
#include <cuda_runtime.h>
#include <math.h>
#include <stdint.h>

#define BB 8
#define NN 512
#define KK 32
#define DD 128
#define HH 128
#define PP 8
#define NODES (BB*NN)

// Scratch (allocation-free rule: __device__ globals)
__device__ float g_pg[NODES*PP*3];   // global points per node
__device__ float g_R[NODES*9];       // frames
__device__ float g_t[NODES*3];       // translations
__device__ float g_s1[NODES*HH];     // static part of layer-1 pre-activation (incl bias)

// fragment-packed tf32 weights: [ng][ks][nth][lane] -> float4(b0_a,b1_a,b0_b,b1_b)
__device__ float4 g_w1e_f[2*32*4*32];   // Wm1 rows 128..383 (K=256, KS=32)
__device__ float4 g_w1g_f[2*5*4*32];    // Wm1 rows 416..455 (K=40, KS=5)
__device__ float4 g_w2_f[2*16*4*32];    // Wm2 (K=128, KS=16)
__device__ float4 g_w3_f[2*16*4*32];    // Wm3

__device__ __forceinline__ uint32_t f2tf32(float f) {
    uint32_t o;
    asm("cvt.rna.tf32.f32 %0, %1;" : "=r"(o) : "f"(f));
    return o;
}

// ---------------------------------------------------------------------------
// Kernel 0: pack weights into mma-fragment order (tf32-rounded)
// ---------------------------------------------------------------------------
__device__ __forceinline__ float4 pack4(const float* __restrict__ W, int i, int KS) {
    int lane = i & 31;
    int nth  = (i >> 5) & 3;
    int rest = i >> 7;
    int ks = rest % KS;
    int ng = rest / KS;
    int gid = lane >> 2, q = lane & 3;
    int k0 = ks * 8;
    int na = ng*64 + nth*16 + gid;
    float4 o;
    o.x = __uint_as_float(f2tf32(W[(k0+q)*128 + na]));
    o.y = __uint_as_float(f2tf32(W[(k0+q+4)*128 + na]));
    o.z = __uint_as_float(f2tf32(W[(k0+q)*128 + na + 8]));
    o.w = __uint_as_float(f2tf32(W[(k0+q+4)*128 + na + 8]));
    return o;
}

__global__ void weight_prep(const float* __restrict__ Wm1,
                            const float* __restrict__ Wm2,
                            const float* __restrict__ Wm3)
{
    int i = blockIdx.x * blockDim.x + threadIdx.x;
    if (i < 2*32*4*32) g_w1e_f[i] = pack4(Wm1 + 128*128, i, 32);
    if (i < 2*16*4*32) {
        g_w2_f[i] = pack4(Wm2, i, 16);
        g_w3_f[i] = pack4(Wm3, i, 16);
    }
    if (i < 2*5*4*32)  g_w1g_f[i] = pack4(Wm1 + 416*128, i, 5);
}

// ---------------------------------------------------------------------------
// Kernel 1: per-node frame + points + static layer-1, 4 nodes per CTA
// ---------------------------------------------------------------------------
__global__ void node_prep_kernel(const float* __restrict__ hV_g,
                                 const float* __restrict__ X,
                                 const float* __restrict__ Wp,
                                 const float* __restrict__ bp,
                                 const float* __restrict__ Wm1,
                                 const float* __restrict__ bm1)
{
    int node0 = blockIdx.x * 4;
    int t = threadIdx.x;
    __shared__ float hv4[4*128];
    __shared__ float pl4[4*24];
    __shared__ float pln4[4*8];
    __shared__ float Rn4[4*9];
    __shared__ float tn4[4*3];

    #pragma unroll
    for (int nn = 0; nn < 4; ++nn)
        hv4[nn*128 + t] = hV_g[(size_t)(node0+nn)*DD + t];
    __syncthreads();

    if (t < 96) {
        int nn = t / 24, j = t % 24;
        float acc = bp[j];
        #pragma unroll 8
        for (int d = 0; d < DD; ++d) acc += hv4[nn*128 + d] * Wp[d*24 + j];
        pl4[nn*24 + j] = acc;
    } else if (t < 100) {
        int nn = t - 96;
        const float* x = X + (size_t)(node0+nn)*9;
        float Xn0=x[0],Xn1=x[1],Xn2=x[2];
        float Xa0=x[3],Xa1=x[4],Xa2=x[5];
        float Xc0=x[6],Xc1=x[7],Xc2=x[8];
        float v10=Xc0-Xa0, v11=Xc1-Xa1, v12=Xc2-Xa2;
        float v20=Xn0-Xa0, v21=Xn1-Xa1, v22=Xn2-Xa2;
        float inv1 = rsqrtf(v10*v10+v11*v11+v12*v12+1e-8f);
        float e10=v10*inv1, e11=v11*inv1, e12=v12*inv1;
        float dp = e10*v20+e11*v21+e12*v22;
        float u20=v20-e10*dp, u21=v21-e11*dp, u22=v22-e12*dp;
        float inv2 = rsqrtf(u20*u20+u21*u21+u22*u22+1e-8f);
        float e20=u20*inv2, e21=u21*inv2, e22=u22*inv2;
        float e30=e11*e22-e12*e21;
        float e31=e12*e20-e10*e22;
        float e32=e10*e21-e11*e20;
        float* Rn = Rn4 + nn*9;
        Rn[0]=e10; Rn[1]=e20; Rn[2]=e30;
        Rn[3]=e11; Rn[4]=e21; Rn[5]=e31;
        Rn[6]=e12; Rn[7]=e22; Rn[8]=e32;
        tn4[nn*3+0]=Xa0*0.1f; tn4[nn*3+1]=Xa1*0.1f; tn4[nn*3+2]=Xa2*0.1f;
    }
    __syncthreads();

    if (t < 32) {
        int nn = t >> 3, p = t & 7;
        float a=pl4[nn*24+p*3+0], b=pl4[nn*24+p*3+1], c=pl4[nn*24+p*3+2];
        pln4[nn*8+p] = sqrtf(a*a+b*b+c*c + 1e-8f);
    }
    __syncthreads();

    if (t < 96) {
        int nn = t / 24, j = t % 24;
        int p = j/3, i = j%3;
        const float* Rn = Rn4 + nn*9;
        float pg = tn4[nn*3+i] + Rn[i*3+0]*pl4[nn*24+p*3+0]
                 + Rn[i*3+1]*pl4[nn*24+p*3+1] + Rn[i*3+2]*pl4[nn*24+p*3+2];
        g_pg[(size_t)(node0+nn)*24 + j] = pg;
    }
    if (t < 36) g_R[(size_t)node0*9 + t] = Rn4[t];
    if (t < 12) g_t[(size_t)node0*3 + t] = tn4[t];

    // static layer-1 contribution for 4 nodes (fp32)
    float s0 = bm1[t], s1v = s0, s2 = s0, s3 = s0;
    #pragma unroll 4
    for (int d = 0; d < DD; ++d) {
        float wv = Wm1[d*HH + t];
        s0  = fmaf(hv4[d],       wv, s0);
        s1v = fmaf(hv4[128+d],   wv, s1v);
        s2  = fmaf(hv4[256+d],   wv, s2);
        s3  = fmaf(hv4[384+d],   wv, s3);
    }
    #pragma unroll
    for (int j = 0; j < 24; ++j) {
        float wv = Wm1[(384+j)*HH + t];
        s0  = fmaf(pl4[j],    wv, s0);
        s1v = fmaf(pl4[24+j], wv, s1v);
        s2  = fmaf(pl4[48+j], wv, s2);
        s3  = fmaf(pl4[72+j], wv, s3);
    }
    #pragma unroll
    for (int p = 0; p < 8; ++p) {
        float wv = Wm1[(408+p)*HH + t];
        s0  = fmaf(pln4[p],    wv, s0);
        s1v = fmaf(pln4[8+p],  wv, s1v);
        s2  = fmaf(pln4[16+p], wv, s2);
        s3  = fmaf(pln4[24+p], wv, s3);
    }
    g_s1[(size_t)node0*HH + t]       = s0;
    g_s1[(size_t)(node0+1)*HH + t]   = s1v;
    g_s1[(size_t)(node0+2)*HH + t]   = s2;
    g_s1[(size_t)(node0+3)*HH + t]   = s3;
}

// ---------------------------------------------------------------------------
// mma over packed fragments. r0/r1: smem row ptrs (incl +q). frag: packed B
// (already offset by ng and lane). 8 n-tiles per warp.
// ---------------------------------------------------------------------------
__device__ __forceinline__ void mma_frag(float (&acc)[8][4],
                                         const float* r0, const float* r1,
                                         const float4* __restrict__ frag,
                                         int ksteps)
{
    #pragma unroll 2
    for (int ks = 0; ks < ksteps; ++ks) {
        uint32_t a0 = __float_as_uint(r0[ks*8]);
        uint32_t a1 = __float_as_uint(r1[ks*8]);
        uint32_t a2 = __float_as_uint(r0[ks*8+4]);
        uint32_t a3 = __float_as_uint(r1[ks*8+4]);
        const float4* fb = frag + ks*128;
        #pragma unroll
        for (int nth = 0; nth < 4; ++nth) {
            float4 b = fb[nth*32];
            uint32_t b0 = __float_as_uint(b.x), b1 = __float_as_uint(b.y);
            uint32_t b2 = __float_as_uint(b.z), b3 = __float_as_uint(b.w);
            asm volatile(
                "mma.sync.aligned.m16n8k8.row.col.f32.tf32.tf32.f32 "
                "{%0,%1,%2,%3},{%4,%5,%6,%7},{%8,%9},{%0,%1,%2,%3};"
                : "+f"(acc[2*nth][0]), "+f"(acc[2*nth][1]), "+f"(acc[2*nth][2]), "+f"(acc[2*nth][3])
                : "r"(a0), "r"(a1), "r"(a2), "r"(a3), "r"(b0), "r"(b1));
            asm volatile(
                "mma.sync.aligned.m16n8k8.row.col.f32.tf32.tf32.f32 "
                "{%0,%1,%2,%3},{%4,%5,%6,%7},{%8,%9},{%0,%1,%2,%3};"
                : "+f"(acc[2*nth+1][0]), "+f"(acc[2*nth+1][1]), "+f"(acc[2*nth+1][2]), "+f"(acc[2*nth+1][3])
                : "r"(a0), "r"(a1), "r"(a2), "r"(a3), "r"(b2), "r"(b3));
        }
    }
}

__device__ __forceinline__ float warp_sum(float v) {
    #pragma unroll
    for (int o = 16; o; o >>= 1) v += __shfl_xor_sync(0xffffffffu, v, o);
    return v;
}

// smem layout (floats), 2 nodes / CTA, 64 edges
#define ASTRIDE 132
#define GSTRIDE 44
#define SM_BUFA  0          // 64*132 = 8448
#define SM_BUFB  8448       // 8448
#define SM_GEO   16896      // 64*44 = 2816
#define SM_HV    19712      // 256
#define SM_S1    19968      // 256
#define SM_HS    20224      // 256
#define SM_D1    20480      // 1024
#define SM_RN    21504      // 24
#define SM_TN    21528      // 8
#define SM_PGN   21536      // 48
#define SM_MA    21584      // 64
#define SM_RED   21648      // 16
#define SM_PD    21664      // 1024
#define SM_EIX   22688      // 64 ints
#define SM_FLOATS 22752
#define SMEM_BYTES (SM_FLOATS*4)

// ---------------------------------------------------------------------------
// Kernel 2: 2 nodes per CTA. 8 warps: mh = w&3 (16-edge m-tile of 64),
// ng = w>>2 (64-col group). node of m-tile = mh>>1.
// ---------------------------------------------------------------------------
__global__ void __launch_bounds__(256, 2)
msg_kernel(const float* __restrict__ hV_g, const float* __restrict__ hE_g,
           const float* __restrict__ maskV_g, const float* __restrict__ maskA_g,
           const float* __restrict__ bm2, const float* __restrict__ bm3,
           const float* __restrict__ g1, const float* __restrict__ be1,
           const float* __restrict__ Wd1, const float* __restrict__ bd1,
           const float* __restrict__ Wd2, const float* __restrict__ bd2,
           const float* __restrict__ g2, const float* __restrict__ be2,
           const int* __restrict__ Eidx, float* __restrict__ out)
{
    extern __shared__ float sm[];
    float* bufA = sm + SM_BUFA;
    float* bufB = sm + SM_BUFB;
    float* geo = sm + SM_GEO;
    float* hv  = sm + SM_HV;
    float* s1  = sm + SM_S1;
    float* hs  = sm + SM_HS;
    float* d1s = sm + SM_D1;
    float* Rn  = sm + SM_RN;
    float* tn  = sm + SM_TN;
    float* pgn = sm + SM_PGN;
    float* mA  = sm + SM_MA;
    float* red = sm + SM_RED;
    float* pd  = sm + SM_PD;
    int*   eix = (int*)(sm + SM_EIX);

    int node0 = blockIdx.x * 2;
    int batch = node0 / NN;
    int t = threadIdx.x;
    int w = t >> 5, lane = t & 31;
    int mh = w & 3, ng = w >> 2;
    int gid = lane >> 2, q = lane & 3;

    hv[t] = hV_g[(size_t)node0*DD + t];
    s1[t] = g_s1[(size_t)node0*HH + t];
    if (t < 48) pgn[t] = g_pg[(size_t)node0*24 + t];
    else if (t < 66) Rn[t-48] = g_R[(size_t)node0*9 + (t-48)];
    else if (t < 72) tn[t-66] = g_t[(size_t)node0*3 + (t-66)];
    if (t >= 128 && t < 192) mA[t-128] = maskA_g[(size_t)node0*KK + (t-128)];
    else if (t >= 192) eix[t-192] = Eidx[(size_t)node0*KK + (t-192)];
    __syncthreads();

    // ---------------- stage h_E (64 rows, coalesced, tf32) ----------------
    {
        const float4* src = (const float4*)(hE_g + (size_t)node0*KK*DD);
        #pragma unroll
        for (int i = 0; i < 8; ++i) {
            int f4 = t + i*256;          // 0..2047
            float4 v = src[f4];
            int e = f4 >> 5, c = (f4 & 31) * 4;
            float4 o;
            o.x = __uint_as_float(f2tf32(v.x));
            o.y = __uint_as_float(f2tf32(v.y));
            o.z = __uint_as_float(f2tf32(v.z));
            o.w = __uint_as_float(f2tf32(v.w));
            *(float4*)(bufA + e*ASTRIDE + c) = o;
        }
    }
    // geometry rows: warp w handles edges w, w+8, ..., w+56
    #pragma unroll
    for (int ii = 0; ii < 8; ++ii) {
        int e = w + ii*8;
        if (lane < 8) {
            int p = lane;
            int nn = e >> 5;
            int j = eix[e];
            const float* qg = g_pg + (size_t)(batch*NN + j)*24 + p*3;
            float q0 = qg[0], q1 = qg[1], q2 = qg[2];
            const float* R = Rn + nn*9;
            float d0 = pgn[nn*24+p*3+0]-q0, d1 = pgn[nn*24+p*3+1]-q1, d2 = pgn[nn*24+p*3+2]-q2;
            float cc0 = q0 - tn[nn*3+0], cc1 = q1 - tn[nn*3+1], cc2 = q2 - tn[nn*3+2];
            float l0 = R[0]*cc0 + R[3]*cc1 + R[6]*cc2;
            float l1 = R[1]*cc0 + R[4]*cc1 + R[7]*cc2;
            float l2 = R[2]*cc0 + R[5]*cc1 + R[8]*cc2;
            float* row = geo + e*GSTRIDE;
            row[p*3+0] = __uint_as_float(f2tf32(l0));
            row[p*3+1] = __uint_as_float(f2tf32(l1));
            row[p*3+2] = __uint_as_float(f2tf32(l2));
            row[24+p] = __uint_as_float(f2tf32(sqrtf(l0*l0+l1*l1+l2*l2 + 1e-8f)));
            row[32+p] = __uint_as_float(f2tf32(sqrtf(d0*d0+d1*d1+d2*d2 + 1e-8f)));
            row[40] = 0.f; row[41] = 0.f; row[42] = 0.f; row[43] = 0.f;
        }
    }
    __syncthreads();

    const float* a_r0 = bufA + (mh*16 + gid)*ASTRIDE + q;
    const float* a_r1 = a_r0 + 8*ASTRIDE;
    const float* b_r0 = bufB + (mh*16 + gid)*ASTRIDE + q;
    const float* b_r1 = b_r0 + 8*ASTRIDE;

    // ---------------- layer 1 phase A: h_E rows ----------------
    float acc[8][4];
    #pragma unroll
    for (int nt = 0; nt < 8; ++nt)
        #pragma unroll
        for (int i = 0; i < 4; ++i) acc[nt][i] = 0.f;

    mma_frag(acc, a_r0, a_r1, g_w1e_f + ng*(32*128) + lane, 16);
    __syncthreads();

    // ---------------- stage nbr_hV (gather, tf32) ----------------
    #pragma unroll
    for (int ii = 0; ii < 8; ++ii) {
        int e = w + ii*8;
        int j = eix[e];
        const float4* src = (const float4*)(hV_g + (size_t)(batch*NN + j)*DD);
        float4 v = src[lane];
        float4 o;
        o.x = __uint_as_float(f2tf32(v.x));
        o.y = __uint_as_float(f2tf32(v.y));
        o.z = __uint_as_float(f2tf32(v.z));
        o.w = __uint_as_float(f2tf32(v.w));
        *(float4*)(bufA + e*ASTRIDE + lane*4) = o;
    }
    __syncthreads();

    // ---------------- layer 1 phase B: nbr_hV + geometry ----------------
    mma_frag(acc, a_r0, a_r1, g_w1e_f + ng*(32*128) + 16*128 + lane, 16);
    {
        const float* g_r0 = geo + (mh*16 + gid)*GSTRIDE + q;
        mma_frag(acc, g_r0, g_r0 + 8*GSTRIDE, g_w1g_f + ng*(5*128) + lane, 5);
    }

    // add static part + relu, store tf32 to bufB
    {
        int e0r = mh*16 + gid;
        const float* s1n = s1 + (mh>>1)*128;
        #pragma unroll
        for (int nt = 0; nt < 8; ++nt) {
            int cb = ng*64 + nt*8 + 2*q;
            float sa = s1n[cb], sb = s1n[cb+1];
            uint2 u0, u1;
            u0.x = f2tf32(fmaxf(acc[nt][0] + sa, 0.f));
            u0.y = f2tf32(fmaxf(acc[nt][1] + sb, 0.f));
            u1.x = f2tf32(fmaxf(acc[nt][2] + sa, 0.f));
            u1.y = f2tf32(fmaxf(acc[nt][3] + sb, 0.f));
            *(uint2*)(bufB + e0r*ASTRIDE + cb) = u0;
            *(uint2*)(bufB + (e0r+8)*ASTRIDE + cb) = u1;
        }
    }
    __syncthreads();

    // ---------------- layer 2 ----------------
    #pragma unroll
    for (int nt = 0; nt < 8; ++nt)
        #pragma unroll
        for (int i = 0; i < 4; ++i) acc[nt][i] = 0.f;
    mma_frag(acc, b_r0, b_r1, g_w2_f + ng*(16*128) + lane, 16);
    {
        int e0r = mh*16 + gid;
        #pragma unroll
        for (int nt = 0; nt < 8; ++nt) {
            int cb = ng*64 + nt*8 + 2*q;
            float ba = bm2[cb], bb = bm2[cb+1];
            uint2 u0, u1;
            u0.x = f2tf32(fmaxf(acc[nt][0] + ba, 0.f));
            u0.y = f2tf32(fmaxf(acc[nt][1] + bb, 0.f));
            u1.x = f2tf32(fmaxf(acc[nt][2] + ba, 0.f));
            u1.y = f2tf32(fmaxf(acc[nt][3] + bb, 0.f));
            *(uint2*)(bufA + e0r*ASTRIDE + cb) = u0;
            *(uint2*)(bufA + (e0r+8)*ASTRIDE + cb) = u1;
        }
    }
    __syncthreads();

    // ---------------- layer 3 (no relu) + masked partial mean ----------------
    #pragma unroll
    for (int nt = 0; nt < 8; ++nt)
        #pragma unroll
        for (int i = 0; i < 4; ++i) acc[nt][i] = 0.f;
    mma_frag(acc, a_r0, a_r1, g_w3_f + ng*(16*128) + lane, 16);
    {
        float mk0 = mA[mh*16 + gid], mk1 = mA[mh*16 + gid + 8];
        #pragma unroll
        for (int nt = 0; nt < 8; ++nt) {
            int cb = ng*64 + nt*8 + 2*q;
            float ba = bm3[cb], bb = bm3[cb+1];
            float ve = (acc[nt][0] + ba)*mk0 + (acc[nt][2] + ba)*mk1;
            float vo = (acc[nt][1] + bb)*mk0 + (acc[nt][3] + bb)*mk1;
            #pragma unroll
            for (int o = 4; o <= 16; o <<= 1) {
                ve += __shfl_xor_sync(0xffffffffu, ve, o);
                vo += __shfl_xor_sync(0xffffffffu, vo, o);
            }
            if (gid == 0) {
                pd[mh*128 + cb] = ve;
                pd[mh*128 + cb + 1] = vo;
            }
        }
    }
    __syncthreads();

    // ---------------- LN1 for both nodes ----------------
    int nodeL = t >> 7, c = t & 127;
    float x, dx;
    {
        float nm = (pd[nodeL*256 + c] + pd[nodeL*256 + 128 + c]) * (1.0f/KK);
        x = hv[nodeL*128 + c] + nm;
        float sA = warp_sum(x);
        if (!lane) red[w] = sA;
    }
    __syncthreads();
    {
        float mu = (red[nodeL*4+0]+red[nodeL*4+1]+red[nodeL*4+2]+red[nodeL*4+3]) * (1.0f/HH);
        dx = x - mu;
        float sB = warp_sum(dx*dx);
        __syncwarp();
        if (!lane) red[8+w] = sB;
    }
    __syncthreads();
    {
        float var = (red[8+nodeL*4]+red[9+nodeL*4]+red[10+nodeL*4]+red[11+nodeL*4]) * (1.0f/HH);
        hs[nodeL*128 + c] = dx * rsqrtf(var + 1e-5f) * g1[c] + be1[c];
    }
    __syncthreads();

    // ---------------- dense1: 128->512 relu, both nodes share weight loads --
    {
        int d0 = t, d1 = t + 256;
        float a00 = bd1[d0], a01 = bd1[d1];
        float a10 = a00, a11 = a01;
        #pragma unroll 4
        for (int r = 0; r < HH; ++r) {
            float w0 = Wd1[r*512 + d0];
            float w1 = Wd1[r*512 + d1];
            float h0 = hs[r], h1 = hs[128 + r];
            a00 = fmaf(h0, w0, a00); a01 = fmaf(h0, w1, a01);
            a10 = fmaf(h1, w0, a10); a11 = fmaf(h1, w1, a11);
        }
        d1s[d0] = fmaxf(a00, 0.f); d1s[d1] = fmaxf(a01, 0.f);
        d1s[512 + d0] = fmaxf(a10, 0.f); d1s[512 + d1] = fmaxf(a11, 0.f);
    }
    __syncthreads();

    // ---------------- dense2: 512->128, 4-way row split, both nodes --------
    {
        int gg = t >> 6;
        int c0 = (t & 63) * 2;
        float oa0=0.f, ob0=0.f, oa1=0.f, ob1=0.f;
        const float* db0 = d1s + gg*128;
        const float* db1 = d1s + 512 + gg*128;
        const float* Wb = Wd2 + (size_t)(gg*128)*128 + c0;
        #pragma unroll 2
        for (int r = 0; r < 128; r += 4) {
            float4 u = *(const float4*)(db0 + r);
            float4 v = *(const float4*)(db1 + r);
            float2 q0 = *(const float2*)(Wb + (r+0)*128);
            float2 q1 = *(const float2*)(Wb + (r+1)*128);
            float2 q2 = *(const float2*)(Wb + (r+2)*128);
            float2 q3 = *(const float2*)(Wb + (r+3)*128);
            oa0 = fmaf(u.x,q0.x,oa0); ob0 = fmaf(u.x,q0.y,ob0);
            oa1 = fmaf(v.x,q0.x,oa1); ob1 = fmaf(v.x,q0.y,ob1);
            oa0 = fmaf(u.y,q1.x,oa0); ob0 = fmaf(u.y,q1.y,ob0);
            oa1 = fmaf(v.y,q1.x,oa1); ob1 = fmaf(v.y,q1.y,ob1);
            oa0 = fmaf(u.z,q2.x,oa0); ob0 = fmaf(u.z,q2.y,ob0);
            oa1 = fmaf(v.z,q2.x,oa1); ob1 = fmaf(v.z,q2.y,ob1);
            oa0 = fmaf(u.w,q3.x,oa0); ob0 = fmaf(u.w,q3.y,ob0);
            oa1 = fmaf(v.w,q3.x,oa1); ob1 = fmaf(v.w,q3.y,ob1);
        }
        pd[gg*128 + c0] = oa0; pd[gg*128 + c0 + 1] = ob0;
        pd[512 + gg*128 + c0] = oa1; pd[512 + gg*128 + c0 + 1] = ob1;
    }
    __syncthreads();

    // ---------------- LN2 + mask ----------------
    float x2, dx2;
    {
        const float* pn = pd + nodeL*512;
        x2 = hs[nodeL*128 + c] + bd2[c] + pn[c] + pn[128+c] + pn[256+c] + pn[384+c];
        float sA = warp_sum(x2);
        if (!lane) red[w] = sA;
    }
    __syncthreads();
    {
        float mu2 = (red[nodeL*4+0]+red[nodeL*4+1]+red[nodeL*4+2]+red[nodeL*4+3]) * (1.0f/HH);
        dx2 = x2 - mu2;
        float sB = warp_sum(dx2*dx2);
        __syncwarp();
        if (!lane) red[8+w] = sB;
    }
    __syncthreads();
    {
        float var2 = (red[8+nodeL*4]+red[9+nodeL*4]+red[10+nodeL*4]+red[11+nodeL*4]) * (1.0f/HH);
        float y = (dx2 * rsqrtf(var2 + 1e-5f) * g2[c] + be2[c]) * maskV_g[node0 + nodeL];
        out[(size_t)(node0 + nodeL)*HH + c] = y;
    }
}

// ---------------------------------------------------------------------------
extern "C" void kernel_launch(void* const* d_in, const int* in_sizes, int n_in,
                              void* d_out, int out_size)
{
    const float* hV    = (const float*)d_in[0];
    const float* hE    = (const float*)d_in[1];
    const float* X     = (const float*)d_in[2];
    const float* maskV = (const float*)d_in[3];
    const float* maskA = (const float*)d_in[4];
    const float* Wp    = (const float*)d_in[5];
    const float* bp    = (const float*)d_in[6];
    const float* Wm1   = (const float*)d_in[7];
    const float* bm1   = (const float*)d_in[8];
    const float* Wm2   = (const float*)d_in[9];
    const float* bm2   = (const float*)d_in[10];
    const float* Wm3   = (const float*)d_in[11];
    const float* bm3   = (const float*)d_in[12];
    const float* g1    = (const float*)d_in[13];
    const float* be1   = (const float*)d_in[14];
    const float* Wd1   = (const float*)d_in[15];
    const float* bd1   = (const float*)d_in[16];
    const float* Wd2   = (const float*)d_in[17];
    const float* bd2   = (const float*)d_in[18];
    const float* g2    = (const float*)d_in[19];
    const float* be2   = (const float*)d_in[20];
    const int*   Eidx  = (const int*)d_in[21];
    float* out = (float*)d_out;

    cudaFuncSetAttribute(msg_kernel, cudaFuncAttributeMaxDynamicSharedMemorySize, SMEM_BYTES);

    weight_prep<<<32, 256>>>(Wm1, Wm2, Wm3);
    node_prep_kernel<<<NODES/4, 128>>>(hV, X, Wp, bp, Wm1, bm1);
    msg_kernel<<<NODES/2, 256, SMEM_BYTES>>>(hV, hE, maskV, maskA,
                                             bm2, bm3, g1, be1,
                                             Wd1, bd1, Wd2, bd2, g2, be2,
                                             Eidx, out);

    // second output: h_E passthrough
    long long hcount = (long long)NODES * HH;
    if ((long long)out_size > hcount) {
        long long n = (long long)out_size - hcount;
        long long emax = (long long)BB*NN*KK*DD;
        if (n > emax) n = emax;
        cudaMemcpyAsync(out + hcount, hE, (size_t)n * sizeof(float),
                        cudaMemcpyDeviceToDevice);
    }
}

// round 6
// speedup vs baseline: 5.0656x; 1.6350x over previous
#include <cuda_runtime.h>
#include <cuda_bf16.h>
#include <math.h>
#include <stdint.h>

#define BB 8
#define NN 512
#define KK 32
#define DD 128
#define HH 128
#define PP 8
#define NODES (BB*NN)

// Scratch (allocation-free rule: __device__ globals)
__device__ float g_pg[NODES*PP*3];
__device__ float g_R[NODES*9];
__device__ float g_t[NODES*3];
__device__ float g_s1[NODES*HH];     // static layer-1 pre-activation (incl bias)
__device__ float g_hs[NODES*HH];     // post-LN1 hidden state

// fragment-packed bf16 weights: [ng][ks][nth][lane] -> uint4(b0a,b1a,b0b,b1b)
__device__ uint4 g_w1e_b[2*16*4*32];   // Wm1 rows 128..383 (K=256, KS=16)
__device__ uint4 g_w1g_b[2*3*4*32];    // Wm1 rows 416..455 (K=40->48, KS=3)
__device__ uint4 g_w2_b[2*8*4*32];     // Wm2 (K=128, KS=8)
__device__ uint4 g_w3_b[2*8*4*32];     // Wm3
__device__ uint4 g_wd1_b[8*8*4*32];    // Wd1 (K=128, N=512: 8 n-groups, KS=8)
__device__ uint4 g_wd2_b[2*32*4*32];   // Wd2 (K=512, N=128: KS=32)

__device__ __forceinline__ uint32_t pkbf(float a, float b) {
    __nv_bfloat162 h = __floats2bfloat162_rn(a, b);
    return *reinterpret_cast<uint32_t*>(&h);
}

// ---------------------------------------------------------------------------
// Kernel 0: pack weights into bf16 mma-fragment order
// ---------------------------------------------------------------------------
__device__ __forceinline__ uint4 packb(const float* __restrict__ W, int ld,
                                       int Krows, int i, int KS)
{
    int lane = i & 31;
    int nth  = (i >> 5) & 3;
    int rest = i >> 7;
    int ks = rest % KS;
    int ng = rest / KS;
    int gid = lane >> 2, q = lane & 3;
    int k0 = ks * 16;
    int na = ng*64 + nth*16 + gid;
    auto f = [&](int k, int n) -> float {
        return (k < Krows) ? W[(size_t)k*ld + n] : 0.f;
    };
    uint4 o;
    o.x = pkbf(f(k0+2*q,   na),   f(k0+2*q+1, na));
    o.y = pkbf(f(k0+2*q+8, na),   f(k0+2*q+9, na));
    o.z = pkbf(f(k0+2*q,   na+8), f(k0+2*q+1, na+8));
    o.w = pkbf(f(k0+2*q+8, na+8), f(k0+2*q+9, na+8));
    return o;
}

__global__ void weight_prep(const float* __restrict__ Wm1,
                            const float* __restrict__ Wm2,
                            const float* __restrict__ Wm3,
                            const float* __restrict__ Wd1,
                            const float* __restrict__ Wd2)
{
    int i = blockIdx.x * blockDim.x + threadIdx.x;
    if (i < 2*16*4*32) g_w1e_b[i] = packb(Wm1 + 128*128, 128, 256, i, 16);
    if (i < 2*8*4*32) {
        g_w2_b[i] = packb(Wm2, 128, 128, i, 8);
        g_w3_b[i] = packb(Wm3, 128, 128, i, 8);
    }
    if (i < 2*3*4*32)  g_w1g_b[i] = packb(Wm1 + 416*128, 128, 40, i, 3);
    if (i < 8*8*4*32)  g_wd1_b[i] = packb(Wd1, 512, 128, i, 8);
    if (i < 2*32*4*32) g_wd2_b[i] = packb(Wd2, 128, 512, i, 32);
}

// ---------------------------------------------------------------------------
// Kernel 1: per-node frame + points + static layer-1, 4 nodes per CTA
// ---------------------------------------------------------------------------
__global__ void node_prep_kernel(const float* __restrict__ hV_g,
                                 const float* __restrict__ X,
                                 const float* __restrict__ Wp,
                                 const float* __restrict__ bp,
                                 const float* __restrict__ Wm1,
                                 const float* __restrict__ bm1)
{
    int node0 = blockIdx.x * 4;
    int t = threadIdx.x;
    __shared__ float hv4[4*128];
    __shared__ float pl4[4*24];
    __shared__ float pln4[4*8];
    __shared__ float Rn4[4*9];
    __shared__ float tn4[4*3];

    #pragma unroll
    for (int nn = 0; nn < 4; ++nn)
        hv4[nn*128 + t] = hV_g[(size_t)(node0+nn)*DD + t];
    __syncthreads();

    if (t < 96) {
        int nn = t / 24, j = t % 24;
        float acc = bp[j];
        #pragma unroll 8
        for (int d = 0; d < DD; ++d) acc += hv4[nn*128 + d] * Wp[d*24 + j];
        pl4[nn*24 + j] = acc;
    } else if (t < 100) {
        int nn = t - 96;
        const float* x = X + (size_t)(node0+nn)*9;
        float Xn0=x[0],Xn1=x[1],Xn2=x[2];
        float Xa0=x[3],Xa1=x[4],Xa2=x[5];
        float Xc0=x[6],Xc1=x[7],Xc2=x[8];
        float v10=Xc0-Xa0, v11=Xc1-Xa1, v12=Xc2-Xa2;
        float v20=Xn0-Xa0, v21=Xn1-Xa1, v22=Xn2-Xa2;
        float inv1 = rsqrtf(v10*v10+v11*v11+v12*v12+1e-8f);
        float e10=v10*inv1, e11=v11*inv1, e12=v12*inv1;
        float dp = e10*v20+e11*v21+e12*v22;
        float u20=v20-e10*dp, u21=v21-e11*dp, u22=v22-e12*dp;
        float inv2 = rsqrtf(u20*u20+u21*u21+u22*u22+1e-8f);
        float e20=u20*inv2, e21=u21*inv2, e22=u22*inv2;
        float e30=e11*e22-e12*e21;
        float e31=e12*e20-e10*e22;
        float e32=e10*e21-e11*e20;
        float* Rn = Rn4 + nn*9;
        Rn[0]=e10; Rn[1]=e20; Rn[2]=e30;
        Rn[3]=e11; Rn[4]=e21; Rn[5]=e31;
        Rn[6]=e12; Rn[7]=e22; Rn[8]=e32;
        tn4[nn*3+0]=Xa0*0.1f; tn4[nn*3+1]=Xa1*0.1f; tn4[nn*3+2]=Xa2*0.1f;
    }
    __syncthreads();

    if (t < 32) {
        int nn = t >> 3, p = t & 7;
        float a=pl4[nn*24+p*3+0], b=pl4[nn*24+p*3+1], c=pl4[nn*24+p*3+2];
        pln4[nn*8+p] = sqrtf(a*a+b*b+c*c + 1e-8f);
    }
    __syncthreads();

    if (t < 96) {
        int nn = t / 24, j = t % 24;
        int p = j/3, i = j%3;
        const float* Rn = Rn4 + nn*9;
        float pg = tn4[nn*3+i] + Rn[i*3+0]*pl4[nn*24+p*3+0]
                 + Rn[i*3+1]*pl4[nn*24+p*3+1] + Rn[i*3+2]*pl4[nn*24+p*3+2];
        g_pg[(size_t)(node0+nn)*24 + j] = pg;
    }
    if (t < 36) g_R[(size_t)node0*9 + t] = Rn4[t];
    if (t < 12) g_t[(size_t)node0*3 + t] = tn4[t];

    float s0 = bm1[t], s1v = s0, s2 = s0, s3 = s0;
    #pragma unroll 4
    for (int d = 0; d < DD; ++d) {
        float wv = Wm1[d*HH + t];
        s0  = fmaf(hv4[d],     wv, s0);
        s1v = fmaf(hv4[128+d], wv, s1v);
        s2  = fmaf(hv4[256+d], wv, s2);
        s3  = fmaf(hv4[384+d], wv, s3);
    }
    #pragma unroll
    for (int j = 0; j < 24; ++j) {
        float wv = Wm1[(384+j)*HH + t];
        s0  = fmaf(pl4[j],    wv, s0);
        s1v = fmaf(pl4[24+j], wv, s1v);
        s2  = fmaf(pl4[48+j], wv, s2);
        s3  = fmaf(pl4[72+j], wv, s3);
    }
    #pragma unroll
    for (int p = 0; p < 8; ++p) {
        float wv = Wm1[(408+p)*HH + t];
        s0  = fmaf(pln4[p],    wv, s0);
        s1v = fmaf(pln4[8+p],  wv, s1v);
        s2  = fmaf(pln4[16+p], wv, s2);
        s3  = fmaf(pln4[24+p], wv, s3);
    }
    g_s1[(size_t)node0*HH + t]     = s0;
    g_s1[(size_t)(node0+1)*HH + t] = s1v;
    g_s1[(size_t)(node0+2)*HH + t] = s2;
    g_s1[(size_t)(node0+3)*HH + t] = s3;
}

// ---------------------------------------------------------------------------
// bf16 m16n8k16 mma helpers
// ---------------------------------------------------------------------------
__device__ __forceinline__ void mma16816(float (&d)[4],
                                         uint32_t a0, uint32_t a1,
                                         uint32_t a2, uint32_t a3,
                                         uint32_t b0, uint32_t b1)
{
    asm volatile(
        "mma.sync.aligned.m16n8k16.row.col.f32.bf16.bf16.f32 "
        "{%0,%1,%2,%3},{%4,%5,%6,%7},{%8,%9},{%0,%1,%2,%3};"
        : "+f"(d[0]), "+f"(d[1]), "+f"(d[2]), "+f"(d[3])
        : "r"(a0), "r"(a1), "r"(a2), "r"(a3), "r"(b0), "r"(b1));
}

// acc: 8 n-tiles (64 cols). r0/r1: smem u32 row ptrs (pre-offset by +q).
// frag: packed B (pre-offset by ng, lane). KSTEPS k16-chunks, chunk = 8 u32.
template<int KSTEPS>
__device__ __forceinline__ void mma_blk(float (*acc)[4],
                                        const uint32_t* r0, const uint32_t* r1,
                                        const uint4* __restrict__ frag)
{
    #pragma unroll
    for (int ks = 0; ks < KSTEPS; ++ks) {
        uint32_t a0 = r0[ks*8], a1 = r1[ks*8], a2 = r0[ks*8+4], a3 = r1[ks*8+4];
        const uint4* fb = frag + ks*128;
        #pragma unroll
        for (int nth = 0; nth < 4; ++nth) {
            uint4 b = fb[nth*32];
            mma16816(acc[2*nth],   a0, a1, a2, a3, b.x, b.y);
            mma16816(acc[2*nth+1], a0, a1, a2, a3, b.z, b.w);
        }
    }
}

__device__ __forceinline__ float warp_sum(float v) {
    #pragma unroll
    for (int o = 16; o; o >>= 1) v += __shfl_xor_sync(0xffffffffu, v, o);
    return v;
}

// msg_kernel smem layout (u32 units)
#define AST 68          // 64 data u32 (128 bf16) + 4 pad
#define GST 28          // 24 data u32 (48 bf16) + 4 pad
#define SM_BUFA  0      // 64*68 = 4352
#define SM_BUFB  4352
#define SM_GEO   8704   // 64*28 = 1792
#define SM_HV    10496  // 256 (fp32)
#define SM_S1    10752  // 256
#define SM_RN    11008  // 24
#define SM_TN    11032  // 8
#define SM_PGN   11040  // 48
#define SM_MA    11088  // 64
#define SM_RED   11152  // 16
#define SM_PD    11168  // 1024
#define SM_EIX   12192  // 64
#define SM_U32   12256
#define SMEM_BYTES (SM_U32*4)

// ---------------------------------------------------------------------------
// Kernel 2: 2 nodes per CTA, bf16 MMA message MLP, ends at LN1 -> g_hs
// 8 warps: mh = w&3 (16-edge m-tile of 64), ng = w>>2 (64-col group)
// ---------------------------------------------------------------------------
__global__ void __launch_bounds__(256, 2)
msg_kernel(const float* __restrict__ hV_g, const float* __restrict__ hE_g,
           const float* __restrict__ maskA_g,
           const float* __restrict__ bm2, const float* __restrict__ bm3,
           const float* __restrict__ g1, const float* __restrict__ be1,
           const int* __restrict__ Eidx)
{
    extern __shared__ float smf[];
    uint32_t* smu = (uint32_t*)smf;
    uint32_t* bufA = smu + SM_BUFA;
    uint32_t* bufB = smu + SM_BUFB;
    uint32_t* geoU = smu + SM_GEO;
    float* hv  = smf + SM_HV;
    float* s1  = smf + SM_S1;
    float* Rn  = smf + SM_RN;
    float* tn  = smf + SM_TN;
    float* pgn = smf + SM_PGN;
    float* mA  = smf + SM_MA;
    float* red = smf + SM_RED;
    float* pd  = smf + SM_PD;
    int*   eix = (int*)(smu + SM_EIX);

    int node0 = blockIdx.x * 2;
    int batch = node0 / NN;
    int t = threadIdx.x;
    int w = t >> 5, lane = t & 31;
    int mh = w & 3, ng = w >> 2;
    int gid = lane >> 2, q = lane & 3;

    hv[t] = hV_g[(size_t)node0*DD + t];
    s1[t] = g_s1[(size_t)node0*HH + t];
    if (t < 48) pgn[t] = g_pg[(size_t)node0*24 + t];
    else if (t < 66) Rn[t-48] = g_R[(size_t)node0*9 + (t-48)];
    else if (t < 72) tn[t-66] = g_t[(size_t)node0*3 + (t-66)];
    if (t >= 128 && t < 192) mA[t-128] = maskA_g[(size_t)node0*KK + (t-128)];
    else if (t >= 192) eix[t-192] = Eidx[(size_t)node0*KK + (t-192)];
    __syncthreads();

    // ---------------- stage h_E (64 rows, coalesced, bf16) ----------------
    {
        const float4* src = (const float4*)(hE_g + (size_t)node0*KK*DD);
        #pragma unroll
        for (int i = 0; i < 8; ++i) {
            int f4 = t + i*256;          // 0..2047
            float4 v = src[f4];
            int e = f4 >> 5, cp = (f4 & 31) * 2;
            uint2 o;
            o.x = pkbf(v.x, v.y);
            o.y = pkbf(v.z, v.w);
            *(uint2*)(bufA + e*AST + cp) = o;
        }
    }
    // geometry rows: warp w handles edges w, w+8, ..., w+56
    #pragma unroll
    for (int ii = 0; ii < 8; ++ii) {
        int e = w + ii*8;
        if (lane < 8) {
            int p = lane;
            int nn = e >> 5;
            int j = eix[e];
            const float* qg = g_pg + (size_t)(batch*NN + j)*24 + p*3;
            float q0 = qg[0], q1 = qg[1], q2 = qg[2];
            const float* R = Rn + nn*9;
            float d0 = pgn[nn*24+p*3+0]-q0, d1 = pgn[nn*24+p*3+1]-q1, d2 = pgn[nn*24+p*3+2]-q2;
            float cc0 = q0 - tn[nn*3+0], cc1 = q1 - tn[nn*3+1], cc2 = q2 - tn[nn*3+2];
            float l0 = R[0]*cc0 + R[3]*cc1 + R[6]*cc2;
            float l1 = R[1]*cc0 + R[4]*cc1 + R[7]*cc2;
            float l2 = R[2]*cc0 + R[5]*cc1 + R[8]*cc2;
            __nv_bfloat16* row = (__nv_bfloat16*)(geoU + e*GST);
            row[p*3+0] = __float2bfloat16_rn(l0);
            row[p*3+1] = __float2bfloat16_rn(l1);
            row[p*3+2] = __float2bfloat16_rn(l2);
            row[24+p] = __float2bfloat16_rn(sqrtf(l0*l0+l1*l1+l2*l2 + 1e-8f));
            row[32+p] = __float2bfloat16_rn(sqrtf(d0*d0+d1*d1+d2*d2 + 1e-8f));
            if (p == 0) {
                uint32_t* ru = geoU + e*GST;
                ru[20] = 0u; ru[21] = 0u; ru[22] = 0u; ru[23] = 0u;
            }
        }
    }
    __syncthreads();

    const uint32_t* a_r0 = bufA + (mh*16 + gid)*AST + q;
    const uint32_t* a_r1 = a_r0 + 8*AST;
    const uint32_t* b_r0 = bufB + (mh*16 + gid)*AST + q;
    const uint32_t* b_r1 = b_r0 + 8*AST;

    // ---------------- layer 1 phase A: h_E rows ----------------
    float acc[8][4];
    #pragma unroll
    for (int nt = 0; nt < 8; ++nt)
        #pragma unroll
        for (int i = 0; i < 4; ++i) acc[nt][i] = 0.f;

    mma_blk<8>(acc, a_r0, a_r1, g_w1e_b + ng*(16*128) + lane);
    __syncthreads();

    // ---------------- stage nbr_hV (gather, bf16) ----------------
    #pragma unroll
    for (int ii = 0; ii < 8; ++ii) {
        int e = w + ii*8;
        int j = eix[e];
        const float4* src = (const float4*)(hV_g + (size_t)(batch*NN + j)*DD);
        float4 v = src[lane];
        uint2 o;
        o.x = pkbf(v.x, v.y);
        o.y = pkbf(v.z, v.w);
        *(uint2*)(bufA + e*AST + lane*2) = o;
    }
    __syncthreads();

    // ---------------- layer 1 phase B: nbr_hV + geometry ----------------
    mma_blk<8>(acc, a_r0, a_r1, g_w1e_b + ng*(16*128) + 8*128 + lane);
    {
        const uint32_t* g_r0 = geoU + (mh*16 + gid)*GST + q;
        mma_blk<3>(acc, g_r0, g_r0 + 8*GST, g_w1g_b + ng*(3*128) + lane);
    }

    // add static part + relu, store bf16 to bufB
    {
        int e0r = mh*16 + gid;
        const float* s1n = s1 + (mh>>1)*128;
        #pragma unroll
        for (int nt = 0; nt < 8; ++nt) {
            int cb = ng*64 + nt*8 + 2*q;
            float sa = s1n[cb], sb = s1n[cb+1];
            bufB[e0r*AST + (cb>>1)] =
                pkbf(fmaxf(acc[nt][0] + sa, 0.f), fmaxf(acc[nt][1] + sb, 0.f));
            bufB[(e0r+8)*AST + (cb>>1)] =
                pkbf(fmaxf(acc[nt][2] + sa, 0.f), fmaxf(acc[nt][3] + sb, 0.f));
        }
    }
    __syncthreads();

    // ---------------- layer 2 ----------------
    #pragma unroll
    for (int nt = 0; nt < 8; ++nt)
        #pragma unroll
        for (int i = 0; i < 4; ++i) acc[nt][i] = 0.f;
    mma_blk<8>(acc, b_r0, b_r1, g_w2_b + ng*(8*128) + lane);
    {
        int e0r = mh*16 + gid;
        #pragma unroll
        for (int nt = 0; nt < 8; ++nt) {
            int cb = ng*64 + nt*8 + 2*q;
            float ba = bm2[cb], bb = bm2[cb+1];
            bufA[e0r*AST + (cb>>1)] =
                pkbf(fmaxf(acc[nt][0] + ba, 0.f), fmaxf(acc[nt][1] + bb, 0.f));
            bufA[(e0r+8)*AST + (cb>>1)] =
                pkbf(fmaxf(acc[nt][2] + ba, 0.f), fmaxf(acc[nt][3] + bb, 0.f));
        }
    }
    __syncthreads();

    // ---------------- layer 3 (no relu) + masked partial mean -------------
    #pragma unroll
    for (int nt = 0; nt < 8; ++nt)
        #pragma unroll
        for (int i = 0; i < 4; ++i) acc[nt][i] = 0.f;
    mma_blk<8>(acc, a_r0, a_r1, g_w3_b + ng*(8*128) + lane);
    {
        float mk0 = mA[mh*16 + gid], mk1 = mA[mh*16 + gid + 8];
        #pragma unroll
        for (int nt = 0; nt < 8; ++nt) {
            int cb = ng*64 + nt*8 + 2*q;
            float ba = bm3[cb], bb = bm3[cb+1];
            float ve = (acc[nt][0] + ba)*mk0 + (acc[nt][2] + ba)*mk1;
            float vo = (acc[nt][1] + bb)*mk0 + (acc[nt][3] + bb)*mk1;
            #pragma unroll
            for (int o = 4; o <= 16; o <<= 1) {
                ve += __shfl_xor_sync(0xffffffffu, ve, o);
                vo += __shfl_xor_sync(0xffffffffu, vo, o);
            }
            if (gid == 0) {
                pd[mh*128 + cb] = ve;
                pd[mh*128 + cb + 1] = vo;
            }
        }
    }
    __syncthreads();

    // ---------------- LN1 for both nodes -> g_hs ----------------
    int nodeL = t >> 7, c = t & 127;
    float x, dx;
    {
        float nm = (pd[nodeL*256 + c] + pd[nodeL*256 + 128 + c]) * (1.0f/KK);
        x = hv[nodeL*128 + c] + nm;
        float sA = warp_sum(x);
        if (!lane) red[w] = sA;
    }
    __syncthreads();
    {
        float mu = (red[nodeL*4+0]+red[nodeL*4+1]+red[nodeL*4+2]+red[nodeL*4+3]) * (1.0f/HH);
        dx = x - mu;
        float sB = warp_sum(dx*dx);
        __syncwarp();
        if (!lane) red[8+w] = sB;
    }
    __syncthreads();
    {
        float var = (red[8+nodeL*4]+red[9+nodeL*4]+red[10+nodeL*4]+red[11+nodeL*4]) * (1.0f/HH);
        g_hs[(size_t)(node0+nodeL)*HH + c] = dx * rsqrtf(var + 1e-5f) * g1[c] + be1[c];
    }
}

// dense kernel smem layout (u32 units)
#define D1ST 260       // 256 data u32 (512 bf16) + 4 pad
#define DM_HSB 0       // 64*68 = 4352
#define DM_D1B 4352    // 64*260 = 16640
#define DM_HSF 20992   // 8192 (fp32)
#define DM_X2  29184   // 8192 (fp32)
#define DM_U32 37376
#define DSMEM_BYTES (DM_U32*4)

// ---------------------------------------------------------------------------
// Kernel 3: dense FFN + LN2 + mask, 64 nodes per CTA, bf16 MMA
// 8 warps: mh = w&3 (16-node m-tile), second index = w>>2
// ---------------------------------------------------------------------------
__global__ void __launch_bounds__(256)
dense_kernel(const float* __restrict__ maskV_g,
             const float* __restrict__ bd1, const float* __restrict__ bd2,
             const float* __restrict__ g2, const float* __restrict__ be2,
             float* __restrict__ out)
{
    extern __shared__ float smf[];
    uint32_t* smu = (uint32_t*)smf;
    uint32_t* hsb = smu + DM_HSB;
    uint32_t* d1b = smu + DM_D1B;
    float* hsf = smf + DM_HSF;
    float* x2s = smf + DM_X2;

    int node0 = blockIdx.x * 64;
    int t = threadIdx.x;
    int w = t >> 5, lane = t & 31;
    int mh = w & 3, ngd = w >> 2;
    int gid = lane >> 2, q = lane & 3;

    // stage hs: fp32 copy + bf16 pack
    {
        const float2* src = (const float2*)(g_hs + (size_t)node0*HH);
        #pragma unroll
        for (int i = t; i < 4096; i += 256) {
            float2 v = src[i];
            int row = i >> 6, cp = i & 63;
            hsf[row*128 + cp*2]     = v.x;
            hsf[row*128 + cp*2 + 1] = v.y;
            hsb[row*AST + cp] = pkbf(v.x, v.y);
        }
    }
    __syncthreads();

    const uint32_t* a_r0 = hsb + (mh*16 + gid)*AST + q;
    const uint32_t* a_r1 = a_r0 + 8*AST;

    // ---------------- dense1: 128 -> 512, relu, bf16 out ----------------
    #pragma unroll
    for (int p = 0; p < 2; ++p) {
        float acc[16][4];
        #pragma unroll
        for (int nt = 0; nt < 16; ++nt)
            #pragma unroll
            for (int i = 0; i < 4; ++i) acc[nt][i] = 0.f;
        #pragma unroll
        for (int h = 0; h < 2; ++h) {
            int ngrp = p*4 + ngd*2 + h;
            mma_blk<8>(acc + h*8, a_r0, a_r1, g_wd1_b + ngrp*(8*128) + lane);
        }
        int e0r = mh*16 + gid;
        #pragma unroll
        for (int h = 0; h < 2; ++h) {
            #pragma unroll
            for (int nt = 0; nt < 8; ++nt) {
                int cb = p*256 + ngd*128 + h*64 + nt*8 + 2*q;
                float ba = bd1[cb], bb = bd1[cb+1];
                float* a4 = acc[h*8 + nt];
                d1b[e0r*D1ST + (cb>>1)] =
                    pkbf(fmaxf(a4[0] + ba, 0.f), fmaxf(a4[1] + bb, 0.f));
                d1b[(e0r+8)*D1ST + (cb>>1)] =
                    pkbf(fmaxf(a4[2] + ba, 0.f), fmaxf(a4[3] + bb, 0.f));
            }
        }
    }
    __syncthreads();

    // ---------------- dense2: 512 -> 128, + bd2 + residual ----------------
    {
        float acc[8][4];
        #pragma unroll
        for (int nt = 0; nt < 8; ++nt)
            #pragma unroll
            for (int i = 0; i < 4; ++i) acc[nt][i] = 0.f;
        const uint32_t* d_r0 = d1b + (mh*16 + gid)*D1ST + q;
        const uint32_t* d_r1 = d_r0 + 8*D1ST;
        const uint4* frag = g_wd2_b + ngd*(32*128) + lane;
        #pragma unroll 4
        for (int ks = 0; ks < 32; ++ks) {
            uint32_t a0 = d_r0[ks*8], a1 = d_r1[ks*8], a2 = d_r0[ks*8+4], a3 = d_r1[ks*8+4];
            const uint4* fb = frag + ks*128;
            #pragma unroll
            for (int nth = 0; nth < 4; ++nth) {
                uint4 b = fb[nth*32];
                mma16816(acc[2*nth],   a0, a1, a2, a3, b.x, b.y);
                mma16816(acc[2*nth+1], a0, a1, a2, a3, b.z, b.w);
            }
        }
        int r0 = mh*16 + gid, r1 = r0 + 8;
        #pragma unroll
        for (int nt = 0; nt < 8; ++nt) {
            int cb = ngd*64 + nt*8 + 2*q;
            float ba = bd2[cb], bb = bd2[cb+1];
            x2s[r0*128 + cb]     = acc[nt][0] + ba + hsf[r0*128 + cb];
            x2s[r0*128 + cb + 1] = acc[nt][1] + bb + hsf[r0*128 + cb + 1];
            x2s[r1*128 + cb]     = acc[nt][2] + ba + hsf[r1*128 + cb];
            x2s[r1*128 + cb + 1] = acc[nt][3] + bb + hsf[r1*128 + cb + 1];
        }
    }
    __syncthreads();

    // ---------------- LN2 + mask: warp w handles nodes w*8..w*8+7 ----------
    #pragma unroll
    for (int nn = 0; nn < 8; ++nn) {
        int row = w*8 + nn;
        float v0 = x2s[row*128 + lane];
        float v1 = x2s[row*128 + lane + 32];
        float v2 = x2s[row*128 + lane + 64];
        float v3 = x2s[row*128 + lane + 96];
        float mu = warp_sum(v0+v1+v2+v3) * (1.0f/HH);
        float d0 = v0-mu, d1 = v1-mu, d2 = v2-mu, d3 = v3-mu;
        float var = warp_sum(d0*d0+d1*d1+d2*d2+d3*d3) * (1.0f/HH);
        float rs = rsqrtf(var + 1e-5f);
        float mk = maskV_g[node0 + row];
        float* o = out + (size_t)(node0 + row)*HH;
        o[lane]      = (d0*rs*g2[lane]      + be2[lane])      * mk;
        o[lane + 32] = (d1*rs*g2[lane + 32] + be2[lane + 32]) * mk;
        o[lane + 64] = (d2*rs*g2[lane + 64] + be2[lane + 64]) * mk;
        o[lane + 96] = (d3*rs*g2[lane + 96] + be2[lane + 96]) * mk;
    }
}

// ---------------------------------------------------------------------------
extern "C" void kernel_launch(void* const* d_in, const int* in_sizes, int n_in,
                              void* d_out, int out_size)
{
    const float* hV    = (const float*)d_in[0];
    const float* hE    = (const float*)d_in[1];
    const float* X     = (const float*)d_in[2];
    const float* maskV = (const float*)d_in[3];
    const float* maskA = (const float*)d_in[4];
    const float* Wp    = (const float*)d_in[5];
    const float* bp    = (const float*)d_in[6];
    const float* Wm1   = (const float*)d_in[7];
    const float* bm1   = (const float*)d_in[8];
    const float* Wm2   = (const float*)d_in[9];
    const float* bm2   = (const float*)d_in[10];
    const float* Wm3   = (const float*)d_in[11];
    const float* bm3   = (const float*)d_in[12];
    const float* g1    = (const float*)d_in[13];
    const float* be1   = (const float*)d_in[14];
    const float* Wd1   = (const float*)d_in[15];
    const float* bd1   = (const float*)d_in[16];
    const float* Wd2   = (const float*)d_in[17];
    const float* bd2   = (const float*)d_in[18];
    const float* g2    = (const float*)d_in[19];
    const float* be2   = (const float*)d_in[20];
    const int*   Eidx  = (const int*)d_in[21];
    float* out = (float*)d_out;

    cudaFuncSetAttribute(msg_kernel, cudaFuncAttributeMaxDynamicSharedMemorySize, SMEM_BYTES);
    cudaFuncSetAttribute(dense_kernel, cudaFuncAttributeMaxDynamicSharedMemorySize, DSMEM_BYTES);

    weight_prep<<<32, 256>>>(Wm1, Wm2, Wm3, Wd1, Wd2);
    node_prep_kernel<<<NODES/4, 128>>>(hV, X, Wp, bp, Wm1, bm1);
    msg_kernel<<<NODES/2, 256, SMEM_BYTES>>>(hV, hE, maskA, bm2, bm3,
                                             g1, be1, Eidx);
    dense_kernel<<<NODES/64, 256, DSMEM_BYTES>>>(maskV, bd1, bd2, g2, be2, out);

    // second output: h_E passthrough
    long long hcount = (long long)NODES * HH;
    if ((long long)out_size > hcount) {
        long long n = (long long)out_size - hcount;
        long long emax = (long long)BB*NN*KK*DD;
        if (n > emax) n = emax;
        cudaMemcpyAsync(out + hcount, hE, (size_t)n * sizeof(float),
                        cudaMemcpyDeviceToDevice);
    }
}